// round 1
// baseline (speedup 1.0000x reference)
#include <cuda_runtime.h>
#include <cstdint>

// ---------------- problem constants ----------------
#define BB   4
#define TT   1024
#define CC   1024
#define NH   16
#define NKV  4
#define HD   64
#define EE   8
#define FF   4096
#define WIN  256
#define NTOK (BB*TT)          // 4096
#define EPS  1e-6f

// ---------------- scratch (device globals; no allocs allowed) ----------------
__device__ float g_hn  [(size_t)NTOK*CC];        // attn-rmsnorm output
__device__ float g_q   [(size_t)NTOK*NH*HD];
__device__ float g_k   [(size_t)NTOK*NKV*HD];
__device__ float g_v   [(size_t)NTOK*NKV*HD];
__device__ float g_att [(size_t)NTOK*CC];
__device__ float g_hres[(size_t)NTOK*CC];        // x + attn
__device__ float g_gbuf[(size_t)NTOK*CC];        // ffn-rmsnorm output
__device__ int   g_counts[EE];
__device__ int   g_tok [(size_t)EE*NTOK];        // per-expert token lists
__device__ int   g_tidx[(size_t)NTOK*2];
__device__ int   g_tpos[(size_t)NTOK*2];
__device__ float g_twt [(size_t)NTOK*2];
__device__ float g_hid [(size_t)EE*NTOK*FF];     // 512 MB
__device__ float g_moe [(size_t)EE*NTOK*CC];     // 128 MB

// ---------------- small kernels ----------------
__global__ void zero_counts_kernel() {
    if (threadIdx.x < EE) g_counts[threadIdx.x] = 0;
}

__global__ void rmsnorm_kernel(const float* __restrict__ x,
                               const float* __restrict__ w,
                               float* __restrict__ o) {
    int row = blockIdx.x;
    const float* xr = x + (size_t)row * CC;
    __shared__ float red[8];
    float s = 0.f;
    for (int c = threadIdx.x; c < CC; c += 256) { float v = xr[c]; s += v * v; }
    #pragma unroll
    for (int off = 16; off; off >>= 1) s += __shfl_xor_sync(~0u, s, off);
    if ((threadIdx.x & 31) == 0) red[threadIdx.x >> 5] = s;
    __syncthreads();
    if (threadIdx.x < 8) {
        float t = red[threadIdx.x];
        #pragma unroll
        for (int off = 4; off; off >>= 1) t += __shfl_xor_sync(0xff, t, off);
        if (threadIdx.x == 0) red[0] = t;
    }
    __syncthreads();
    float inv = rsqrtf(red[0] * (1.0f / CC) + EPS);
    for (int c = threadIdx.x; c < CC; c += 256)
        o[(size_t)row * CC + c] = xr[c] * inv * w[c];
}

// RoPE applied in-place to [NTOK, nh, HD]; pair (d, d+32)
__global__ void rope_kernel(float* __restrict__ t, int nh) {
    int idx = blockIdx.x * blockDim.x + threadIdx.x;
    int total = NTOK * nh * 32;
    if (idx >= total) return;
    int n = idx / (nh * 32);
    int r = idx - n * (nh * 32);
    int h = r >> 5;
    int d = r & 31;
    int pos = n & (TT - 1);                  // n = b*T + t
    float* p = t + ((size_t)n * nh + h) * HD;
    float fr  = __powf(10000.0f, -(float)d * (1.0f / 32.0f));
    float ang = (float)pos * fr;
    float cs = cosf(ang), sn = sinf(ang);
    float x1 = p[d], x2 = p[d + 32];
    p[d]      = x1 * cs - x2 * sn;
    p[d + 32] = x2 * cs + x1 * sn;
}

// ---------------- generic tiled fp32 GEMM: C = A@W (+res) ----------------
#define BM 128
#define BN 64
#define BK 16

__global__ void gemm_kernel(const float* __restrict__ A,
                            const float* __restrict__ W,
                            float* __restrict__ Co,
                            const float* __restrict__ res,
                            int K, int Nc) {
    __shared__ float As[BK][BM];
    __shared__ float Bs[BK][BN];
    int tid = threadIdx.x;
    int tx = tid & 15, ty = tid >> 4;
    int m0 = blockIdx.y * BM;
    int n0 = blockIdx.x * BN;
    float acc[8][4] = {};
    int lrow = tid >> 1;                     // row this thread loads
    int kq0  = (tid & 1) * 2;                // float4 slot 0/1 or 2/3
    const float* Arow = A + (size_t)(m0 + lrow) * K;
    int krow = tid >> 4, nq = tid & 15;

    for (int k0 = 0; k0 < K; k0 += BK) {
        #pragma unroll
        for (int i = 0; i < 2; i++) {
            float4 a = *(const float4*)&Arow[k0 + (kq0 + i) * 4];
            int kb = (kq0 + i) * 4;
            As[kb + 0][lrow] = a.x; As[kb + 1][lrow] = a.y;
            As[kb + 2][lrow] = a.z; As[kb + 3][lrow] = a.w;
        }
        *(float4*)&Bs[krow][nq * 4] =
            *(const float4*)&W[(size_t)(k0 + krow) * Nc + n0 + nq * 4];
        __syncthreads();
        #pragma unroll
        for (int k = 0; k < BK; k++) {
            float ra[8], rb[4];
            #pragma unroll
            for (int i = 0; i < 8; i++) ra[i] = As[k][ty * 8 + i];
            #pragma unroll
            for (int j = 0; j < 4; j++) rb[j] = Bs[k][tx * 4 + j];
            #pragma unroll
            for (int i = 0; i < 8; i++)
                #pragma unroll
                for (int j = 0; j < 4; j++)
                    acc[i][j] += ra[i] * rb[j];
        }
        __syncthreads();
    }
    #pragma unroll
    for (int i = 0; i < 8; i++) {
        int m = m0 + ty * 8 + i;
        #pragma unroll
        for (int j = 0; j < 4; j++) {
            int n = n0 + tx * 4 + j;
            float vv = acc[i][j];
            if (res) vv += res[(size_t)m * Nc + n];
            Co[(size_t)m * Nc + n] = vv;
        }
    }
}

// ---------------- attention: sliding-window causal, GQA ----------------
#define QT 128
#define KT 32

__global__ __launch_bounds__(QT)
void attn_kernel(const float* __restrict__ q, const float* __restrict__ k,
                 const float* __restrict__ v, float* __restrict__ out) {
    int bh = blockIdx.y;
    int b = bh / NH, h = bh - b * NH;
    int kh = h / (NH / NKV);
    int q0 = blockIdx.x * QT;
    int tid = threadIdx.x;
    int i = q0 + tid;

    __shared__ float Ks[KT][HD];
    __shared__ float Vs[KT][HD];

    float qr[HD];
    const float* qrow = q + ((size_t)(b * TT + i) * NH + h) * HD;
    #pragma unroll
    for (int d = 0; d < HD; d++) qr[d] = qrow[d] * 0.125f;   // 1/sqrt(64)

    float acc[HD];
    #pragma unroll
    for (int d = 0; d < HD; d++) acc[d] = 0.f;
    float mx = -1e30f, l = 0.f;

    int kmin = q0 - WIN + 1; if (kmin < 0) kmin = 0;
    kmin &= ~(KT - 1);
    int kmax = q0 + QT - 1;

    for (int kt = kmin; kt <= kmax; kt += KT) {
        __syncthreads();
        #pragma unroll
        for (int u = 0; u < 4; u++) {
            int idx = tid + u * QT;          // 0..511 float4 slots
            int r = idx >> 4;
            int c = (idx & 15) * 4;
            const float* kr = k + ((size_t)(b * TT + kt + r) * NKV + kh) * HD;
            const float* vr = v + ((size_t)(b * TT + kt + r) * NKV + kh) * HD;
            *(float4*)&Ks[r][c] = *(const float4*)&kr[c];
            *(float4*)&Vs[r][c] = *(const float4*)&vr[c];
        }
        __syncthreads();

        float s[KT];
        float tm = -1e30f;
        #pragma unroll
        for (int kk = 0; kk < KT; kk++) {
            int j = kt + kk;
            bool ok = (j <= i) && (j > i - WIN);
            float d = 0.f;
            #pragma unroll
            for (int dd = 0; dd < HD; dd++) d += qr[dd] * Ks[kk][dd];
            s[kk] = ok ? d : -1e30f;
            tm = fmaxf(tm, s[kk]);
        }
        if (tm > -9e29f) {
            float nm = fmaxf(mx, tm);
            float corr = __expf(mx - nm);    // 0 if mx was -1e30
            l *= corr;
            #pragma unroll
            for (int dd = 0; dd < HD; dd++) acc[dd] *= corr;
            #pragma unroll
            for (int kk = 0; kk < KT; kk++) {
                float p = __expf(s[kk] - nm);   // masked -> exact 0
                l += p;
                #pragma unroll
                for (int dd = 0; dd < HD; dd++) acc[dd] += p * Vs[kk][dd];
            }
            mx = nm;
        }
    }
    float inv = 1.f / l;
    float* orow = out + ((size_t)(b * TT + i) * NH + h) * HD;
    #pragma unroll
    for (int d = 0; d < HD; d++) orow[d] = acc[d] * inv;
}

// ---------------- MoE routing: gate logits, top-2, expert lists ----------------
__global__ void route_kernel(const float* __restrict__ g,
                             const float* __restrict__ gw) {
    int warp = (blockIdx.x * blockDim.x + threadIdx.x) >> 5;
    int lane = threadIdx.x & 31;
    if (warp >= NTOK) return;
    const float* row = g + (size_t)warp * CC;
    float acc[EE] = {};
    for (int kk = lane; kk < CC; kk += 32) {
        float gv = row[kk];
        #pragma unroll
        for (int e = 0; e < EE; e++) acc[e] += gv * gw[kk * EE + e];
    }
    #pragma unroll
    for (int e = 0; e < EE; e++)
        #pragma unroll
        for (int off = 16; off; off >>= 1)
            acc[e] += __shfl_xor_sync(~0u, acc[e], off);
    if (lane == 0) {
        int i0 = 0;
        #pragma unroll
        for (int e = 1; e < EE; e++) if (acc[e] > acc[i0]) i0 = e;
        int i1 = -1;
        #pragma unroll
        for (int e = 0; e < EE; e++)
            if (e != i0 && (i1 < 0 || acc[e] > acc[i1])) i1 = e;
        float m  = acc[i0];
        float p1 = __expf(acc[i1] - m);      // p0 = 1
        float s  = 1.0f + p1;
        float w0 = 1.0f / s, w1 = p1 / s;
        int pos0 = atomicAdd(&g_counts[i0], 1);
        int pos1 = atomicAdd(&g_counts[i1], 1);
        g_tok[i0 * NTOK + pos0] = warp;
        g_tok[i1 * NTOK + pos1] = warp;
        g_tidx[warp * 2 + 0] = i0; g_tidx[warp * 2 + 1] = i1;
        g_tpos[warp * 2 + 0] = pos0; g_tpos[warp * 2 + 1] = pos1;
        g_twt [warp * 2 + 0] = w0;  g_twt [warp * 2 + 1] = w1;
    }
}

// ---------------- MoE GEMM 1: hid = silu(g@w1) * (g@w3), gathered rows ----------------
__global__ void moe13_kernel(const float* __restrict__ w1,
                             const float* __restrict__ w3) {
    int e = blockIdx.z;
    int cnt = g_counts[e];
    int m0 = blockIdx.y * BM;
    if (m0 >= cnt) return;
    int n0 = blockIdx.x * BN;
    const float* W1 = w1 + (size_t)e * CC * FF;
    const float* W3 = w3 + (size_t)e * CC * FF;
    float* hid = g_hid + (size_t)e * NTOK * FF;

    __shared__ float As[BK][BM];
    __shared__ float B1[BK][BN];
    __shared__ float B3[BK][BN];
    int tid = threadIdx.x;
    int tx = tid & 15, ty = tid >> 4;
    int lrow = tid >> 1;
    int kq0  = (tid & 1) * 2;
    int grow = m0 + lrow;
    int tok = (grow < cnt) ? g_tok[e * NTOK + grow] : 0;
    const float* Arow = g_gbuf + (size_t)tok * CC;
    int krow = tid >> 4, nq = tid & 15;

    float a1[8][4] = {}, a3[8][4] = {};
    for (int k0 = 0; k0 < CC; k0 += BK) {
        #pragma unroll
        for (int i = 0; i < 2; i++) {
            float4 a = *(const float4*)&Arow[k0 + (kq0 + i) * 4];
            int kb = (kq0 + i) * 4;
            As[kb + 0][lrow] = a.x; As[kb + 1][lrow] = a.y;
            As[kb + 2][lrow] = a.z; As[kb + 3][lrow] = a.w;
        }
        *(float4*)&B1[krow][nq * 4] =
            *(const float4*)&W1[(size_t)(k0 + krow) * FF + n0 + nq * 4];
        *(float4*)&B3[krow][nq * 4] =
            *(const float4*)&W3[(size_t)(k0 + krow) * FF + n0 + nq * 4];
        __syncthreads();
        #pragma unroll
        for (int k = 0; k < BK; k++) {
            float ra[8], rb1[4], rb3[4];
            #pragma unroll
            for (int i = 0; i < 8; i++) ra[i] = As[k][ty * 8 + i];
            #pragma unroll
            for (int j = 0; j < 4; j++) { rb1[j] = B1[k][tx * 4 + j]; rb3[j] = B3[k][tx * 4 + j]; }
            #pragma unroll
            for (int i = 0; i < 8; i++)
                #pragma unroll
                for (int j = 0; j < 4; j++) {
                    a1[i][j] += ra[i] * rb1[j];
                    a3[i][j] += ra[i] * rb3[j];
                }
        }
        __syncthreads();
    }
    #pragma unroll
    for (int i = 0; i < 8; i++) {
        int m = m0 + ty * 8 + i;
        if (m < cnt) {
            #pragma unroll
            for (int j = 0; j < 4; j++) {
                float x1 = a1[i][j];
                float sig = 1.0f / (1.0f + __expf(-x1));
                hid[(size_t)m * FF + n0 + tx * 4 + j] = x1 * sig * a3[i][j];
            }
        }
    }
}

// ---------------- MoE GEMM 2: moe_out = hid @ w2 ----------------
__global__ void moe2_kernel(const float* __restrict__ w2) {
    int e = blockIdx.z;
    int cnt = g_counts[e];
    int m0 = blockIdx.y * BM;
    if (m0 >= cnt) return;
    int n0 = blockIdx.x * BN;
    const float* A = g_hid + (size_t)e * NTOK * FF;
    const float* W = w2 + (size_t)e * FF * CC;
    float* Co = g_moe + (size_t)e * NTOK * CC;

    __shared__ float As[BK][BM];
    __shared__ float Bs[BK][BN];
    int tid = threadIdx.x;
    int tx = tid & 15, ty = tid >> 4;
    int lrow = tid >> 1;
    int kq0  = (tid & 1) * 2;
    const float* Arow = A + (size_t)(m0 + lrow) * FF;
    int krow = tid >> 4, nq = tid & 15;

    float acc[8][4] = {};
    for (int k0 = 0; k0 < FF; k0 += BK) {
        #pragma unroll
        for (int i = 0; i < 2; i++) {
            float4 a = *(const float4*)&Arow[k0 + (kq0 + i) * 4];
            int kb = (kq0 + i) * 4;
            As[kb + 0][lrow] = a.x; As[kb + 1][lrow] = a.y;
            As[kb + 2][lrow] = a.z; As[kb + 3][lrow] = a.w;
        }
        *(float4*)&Bs[krow][nq * 4] =
            *(const float4*)&W[(size_t)(k0 + krow) * CC + n0 + nq * 4];
        __syncthreads();
        #pragma unroll
        for (int k = 0; k < BK; k++) {
            float ra[8], rb[4];
            #pragma unroll
            for (int i = 0; i < 8; i++) ra[i] = As[k][ty * 8 + i];
            #pragma unroll
            for (int j = 0; j < 4; j++) rb[j] = Bs[k][tx * 4 + j];
            #pragma unroll
            for (int i = 0; i < 8; i++)
                #pragma unroll
                for (int j = 0; j < 4; j++)
                    acc[i][j] += ra[i] * rb[j];
        }
        __syncthreads();
    }
    #pragma unroll
    for (int i = 0; i < 8; i++) {
        int m = m0 + ty * 8 + i;
        if (m < cnt) {
            #pragma unroll
            for (int j = 0; j < 4; j++)
                Co[(size_t)m * CC + n0 + tx * 4 + j] = acc[i][j];
        }
    }
}

// ---------------- final combine: out = hres + sum_j w_j * expert_out ----------------
__global__ void combine_kernel(float* __restrict__ out) {
    int idx = blockIdx.x * blockDim.x + threadIdx.x;   // float4 index over N*C/4
    int n  = idx >> 8;                                  // C/4 = 256
    int c4 = idx & 255;
    int e0 = g_tidx[n * 2], e1 = g_tidx[n * 2 + 1];
    int p0 = g_tpos[n * 2], p1 = g_tpos[n * 2 + 1];
    float w0 = g_twt[n * 2], w1 = g_twt[n * 2 + 1];
    float4 h4 = ((const float4*)g_hres)[idx];
    float4 a = ((const float4*)(g_moe + ((size_t)e0 * NTOK + p0) * CC))[c4];
    float4 b = ((const float4*)(g_moe + ((size_t)e1 * NTOK + p1) * CC))[c4];
    float4 o;
    o.x = h4.x + w0 * a.x + w1 * b.x;
    o.y = h4.y + w0 * a.y + w1 * b.y;
    o.z = h4.z + w0 * a.z + w1 * b.z;
    o.w = h4.w + w0 * a.w + w1 * b.w;
    ((float4*)out)[idx] = o;
}

// ---------------- launch ----------------
extern "C" void kernel_launch(void* const* d_in, const int* in_sizes, int n_in,
                              void* d_out, int out_size) {
    const float* x           = (const float*)d_in[0];
    const float* attn_norm_w = (const float*)d_in[1];
    const float* ffn_norm_w  = (const float*)d_in[2];
    const float* wq          = (const float*)d_in[3];
    const float* wk          = (const float*)d_in[4];
    const float* wv          = (const float*)d_in[5];
    const float* wo          = (const float*)d_in[6];
    const float* gate_w      = (const float*)d_in[7];
    const float* w1          = (const float*)d_in[8];
    const float* w2          = (const float*)d_in[9];
    const float* w3          = (const float*)d_in[10];
    float* out = (float*)d_out;

    float *hn, *qb, *kb, *vb, *att, *hres, *gbuf;
    cudaGetSymbolAddress((void**)&hn,   g_hn);
    cudaGetSymbolAddress((void**)&qb,   g_q);
    cudaGetSymbolAddress((void**)&kb,   g_k);
    cudaGetSymbolAddress((void**)&vb,   g_v);
    cudaGetSymbolAddress((void**)&att,  g_att);
    cudaGetSymbolAddress((void**)&hres, g_hres);
    cudaGetSymbolAddress((void**)&gbuf, g_gbuf);

    zero_counts_kernel<<<1, 32>>>();

    // attn rmsnorm
    rmsnorm_kernel<<<NTOK, 256>>>(x, attn_norm_w, hn);

    // QKV projections
    gemm_kernel<<<dim3(CC / BN, NTOK / BM), 256>>>(hn, wq, qb, nullptr, CC, NH * HD);
    gemm_kernel<<<dim3((NKV * HD) / BN, NTOK / BM), 256>>>(hn, wk, kb, nullptr, CC, NKV * HD);
    gemm_kernel<<<dim3((NKV * HD) / BN, NTOK / BM), 256>>>(hn, wv, vb, nullptr, CC, NKV * HD);

    // RoPE
    rope_kernel<<<(NTOK * NH * 32 + 255) / 256, 256>>>(qb, NH);
    rope_kernel<<<(NTOK * NKV * 32 + 255) / 256, 256>>>(kb, NKV);

    // sliding-window attention
    attn_kernel<<<dim3(TT / QT, BB * NH), QT>>>(qb, kb, vb, att);

    // output projection + residual
    gemm_kernel<<<dim3(CC / BN, NTOK / BM), 256>>>(att, wo, hres, x, CC, CC);

    // ffn rmsnorm
    rmsnorm_kernel<<<NTOK, 256>>>(hres, ffn_norm_w, gbuf);

    // routing (gate logits + top-2 + expert lists)
    route_kernel<<<NTOK / 8, 256>>>(gbuf, gate_w);

    // expert GEMMs (worst-case grids, count-guarded)
    moe13_kernel<<<dim3(FF / BN, NTOK / BM, EE), 256>>>(w1, w3);
    moe2_kernel<<<dim3(CC / BN, NTOK / BM, EE), 256>>>(w2);

    // final combine + residual
    combine_kernel<<<(NTOK * CC / 4) / 256, 256>>>(out);
}

// round 3
// speedup vs baseline: 1.3468x; 1.3468x over previous
#include <cuda_runtime.h>
#include <cstdint>

// ---------------- problem constants ----------------
#define BB   4
#define TT   1024
#define CC   1024
#define NH   16
#define NKV  4
#define HD   64
#define EE   8
#define FF   4096
#define WIN  256
#define NTOK (BB*TT)          // 4096
#define EPS  1e-6f

// ---------------- scratch (device globals; no allocs allowed) ----------------
__device__ float g_hn  [(size_t)NTOK*CC];
__device__ float g_q   [(size_t)NTOK*NH*HD];
__device__ float g_k   [(size_t)NTOK*NKV*HD];
__device__ float g_v   [(size_t)NTOK*NKV*HD];
__device__ float g_att [(size_t)NTOK*CC];
__device__ float g_hres[(size_t)NTOK*CC];
__device__ float g_gbuf[(size_t)NTOK*CC];
__device__ int   g_counts[EE];
__device__ int   g_tok [(size_t)EE*NTOK];
__device__ int   g_tidx[(size_t)NTOK*2];
__device__ int   g_tpos[(size_t)NTOK*2];
__device__ float g_twt [(size_t)NTOK*2];
__device__ float g_hid [(size_t)EE*NTOK*FF];
__device__ float g_moe [(size_t)EE*NTOK*CC];

// ---------------- helpers ----------------
__device__ __forceinline__ uint32_t smem_u32(const void* p) {
    uint32_t a;
    asm("{ .reg .u64 t; cvta.to.shared.u64 t, %1; cvt.u32.u64 %0, t; }" : "=r"(a) : "l"(p));
    return a;
}
__device__ __forceinline__ void cp16(uint32_t dst, const void* src) {
    asm volatile("cp.async.cg.shared.global [%0], [%1], 16;" :: "r"(dst), "l"(src));
}
__device__ __forceinline__ void cp_commit() { asm volatile("cp.async.commit_group;" ::: "memory"); }
__device__ __forceinline__ void cp_wait1() { asm volatile("cp.async.wait_group 1;" ::: "memory"); }
__device__ __forceinline__ void cp_wait0() { asm volatile("cp.async.wait_group 0;" ::: "memory"); }
__device__ __forceinline__ uint32_t f2tf(float f) {
    uint32_t r; asm("cvt.rna.tf32.f32 %0, %1;" : "=r"(r) : "f"(f)); return r;
}
__device__ __forceinline__ void mma8(float* c, const uint32_t* a, const uint32_t* b) {
    asm volatile("mma.sync.aligned.m16n8k8.row.col.f32.tf32.tf32.f32 "
                 "{%0,%1,%2,%3}, {%4,%5,%6,%7}, {%8,%9}, {%0,%1,%2,%3};"
                 : "+f"(c[0]), "+f"(c[1]), "+f"(c[2]), "+f"(c[3])
                 : "r"(a[0]), "r"(a[1]), "r"(a[2]), "r"(a[3]), "r"(b[0]), "r"(b[1]));
}

// ---------------- mma.sync tf32 GEMM ----------------
// block tile 128x128x32, 8 warps (4m x 2n), warp tile 32x64
#define ASTRIDE 36      // floats per A smem row (128 rows)
#define BSTRIDE 136     // floats per B smem row (32 rows)
#define ASZ (128*ASTRIDE)      // floats per A buffer
#define BSZ (32*BSTRIDE)       // floats per B buffer
#define SMEMG ((2*ASZ + 2*BSZ)*4)   // 71680 bytes

// EPI 0: C = acc (+res if res!=null) ; EPI 1: C = silu(acc) * C
template<int EPI>
__global__ __launch_bounds__(256, 2)
void mma_gemm(const float* __restrict__ Abase, const int* __restrict__ glist,
              const float* __restrict__ Wbase, float* __restrict__ Cbase,
              const float* __restrict__ res, int K, int N, int Mtot,
              size_t aStrE, size_t wStrE, size_t cStrE)
{
    int z = blockIdx.z;
    int cnt = (gridDim.z > 1) ? g_counts[z] : Mtot;
    int m0 = blockIdx.y * 128;
    if (m0 >= cnt) return;
    int n0 = blockIdx.x * 128;

    const float* A = Abase + aStrE * z;
    const float* W = Wbase + wStrE * z;
    float*       C = Cbase + cStrE * z;
    const int* list = glist ? (glist + (size_t)z * NTOK) : (const int*)0;

    extern __shared__ float smf[];
    float* Abuf[2] = { smf, smf + ASZ };
    float* Bbuf[2] = { smf + 2 * ASZ, smf + 2 * ASZ + BSZ };

    int tid = threadIdx.x;
    int lane = tid & 31, warp = tid >> 5;
    int wm = warp & 3, wn = warp >> 2;

    // ---- load geometry ----
    int ar = tid >> 1;              // A row 0..127
    int af = (tid & 1) * 4;         // A float4 slot base (0 or 4)
    const float* arow;
    {
        int grow = m0 + ar;
        if (list) { int g2 = (grow < cnt) ? grow : 0; arow = A + (size_t)list[g2] * K; }
        else      arow = A + (size_t)grow * K;
    }
    int bk = tid >> 3;              // B k-row 0..31
    int bf = tid & 7;               // B float4 slot base
    const float* brow = W + (size_t)bk * N + n0 + bf * 4;

    uint32_t aD[2], bD[2];
    #pragma unroll
    for (int p = 0; p < 2; p++) {
        aD[p] = smem_u32(Abuf[p]) + (ar * ASTRIDE + af * 4) * 4;
        bD[p] = smem_u32(Bbuf[p]) + (bk * BSTRIDE + bf * 4) * 4;
    }

    auto load_chunk = [&](int ci, int p) {
        const float* as = arow + ci * 32 + af * 4;
        #pragma unroll
        for (int j = 0; j < 4; j++) cp16(aD[p] + j * 16, as + j * 4);
        const float* bs = brow + (size_t)ci * 32 * N;
        #pragma unroll
        for (int j = 0; j < 4; j++) cp16(bD[p] + j * 128, bs + j * 32);
    };

    float acc[2][8][4];
    #pragma unroll
    for (int mi = 0; mi < 2; mi++)
        #pragma unroll
        for (int ni = 0; ni < 8; ni++)
            #pragma unroll
            for (int q = 0; q < 4; q++) acc[mi][ni][q] = 0.f;

    int lr = lane >> 2, lc = lane & 3;

    auto compute = [&](int p) {
        const float* Am = Abuf[p];
        const float* Bm = Bbuf[p];
        #pragma unroll
        for (int kk = 0; kk < 4; kk++) {
            int kb = kk * 8;
            uint32_t a[2][4], b[8][2];
            #pragma unroll
            for (int mi = 0; mi < 2; mi++) {
                const float* ap = Am + (wm * 32 + mi * 16 + lr) * ASTRIDE + kb + lc;
                a[mi][0] = f2tf(ap[0]);
                a[mi][1] = f2tf(ap[8 * ASTRIDE]);
                a[mi][2] = f2tf(ap[4]);
                a[mi][3] = f2tf(ap[8 * ASTRIDE + 4]);
            }
            #pragma unroll
            for (int ni = 0; ni < 8; ni++) {
                const float* bp = Bm + (kb + lc) * BSTRIDE + wn * 64 + ni * 8 + lr;
                b[ni][0] = f2tf(bp[0]);
                b[ni][1] = f2tf(bp[4 * BSTRIDE]);
            }
            #pragma unroll
            for (int mi = 0; mi < 2; mi++)
                #pragma unroll
                for (int ni = 0; ni < 8; ni++)
                    mma8(acc[mi][ni], a[mi], b[ni]);
        }
    };

    int NC = K / 32;
    load_chunk(0, 0); cp_commit();
    load_chunk(1, 1); cp_commit();
    for (int i = 0; i < NC; i++) {
        int p = i & 1;
        if (i + 2 <= NC) cp_wait1(); else cp_wait0();
        __syncthreads();
        compute(p);
        __syncthreads();
        if (i + 2 < NC) { load_chunk(i + 2, p); cp_commit(); }
    }

    // ---- epilogue ----
    int tc = (lane & 3) * 2;
    #pragma unroll
    for (int mi = 0; mi < 2; mi++) {
        #pragma unroll
        for (int half = 0; half < 2; half++) {
            int m = m0 + wm * 32 + mi * 16 + half * 8 + lr;
            if (m < cnt) {
                float* crow = C + (size_t)m * N + n0 + wn * 64;
                #pragma unroll
                for (int ni = 0; ni < 8; ni++) {
                    float c0 = acc[mi][ni][half * 2 + 0];
                    float c1 = acc[mi][ni][half * 2 + 1];
                    float2* cp2 = (float2*)(crow + ni * 8 + tc);
                    if (EPI == 0) {
                        if (res) {
                            const float2 rr = *(const float2*)(res + (size_t)m * N + n0 + wn * 64 + ni * 8 + tc);
                            c0 += rr.x; c1 += rr.y;
                        }
                        float2 v; v.x = c0; v.y = c1;
                        *cp2 = v;
                    } else {
                        float2 e = *cp2;
                        float2 v;
                        v.x = c0 / (1.f + __expf(-c0)) * e.x;
                        v.y = c1 / (1.f + __expf(-c1)) * e.y;
                        *cp2 = v;
                    }
                }
            }
        }
    }
}

// ---------------- small kernels ----------------
__global__ void zero_counts_kernel() {
    if (threadIdx.x < EE) g_counts[threadIdx.x] = 0;
}

__global__ void rmsnorm_kernel(const float* __restrict__ x,
                               const float* __restrict__ w,
                               float* __restrict__ o) {
    int row = blockIdx.x;
    const float* xr = x + (size_t)row * CC;
    __shared__ float red[8];
    float s = 0.f;
    for (int c = threadIdx.x; c < CC; c += 256) { float v = xr[c]; s += v * v; }
    #pragma unroll
    for (int off = 16; off; off >>= 1) s += __shfl_xor_sync(~0u, s, off);
    if ((threadIdx.x & 31) == 0) red[threadIdx.x >> 5] = s;
    __syncthreads();
    if (threadIdx.x < 8) {
        float t = red[threadIdx.x];
        #pragma unroll
        for (int off = 4; off; off >>= 1) t += __shfl_xor_sync(0xff, t, off);
        if (threadIdx.x == 0) red[0] = t;
    }
    __syncthreads();
    float inv = rsqrtf(red[0] * (1.0f / CC) + EPS);
    for (int c = threadIdx.x; c < CC; c += 256)
        o[(size_t)row * CC + c] = xr[c] * inv * w[c];
}

__global__ void rope_kernel(float* __restrict__ t, int nh) {
    int idx = blockIdx.x * blockDim.x + threadIdx.x;
    int total = NTOK * nh * 32;
    if (idx >= total) return;
    int n = idx / (nh * 32);
    int r = idx - n * (nh * 32);
    int h = r >> 5;
    int d = r & 31;
    int pos = n & (TT - 1);
    float* p = t + ((size_t)n * nh + h) * HD;
    float fr  = __powf(10000.0f, -(float)d * (1.0f / 32.0f));
    float ang = (float)pos * fr;
    float cs = cosf(ang), sn = sinf(ang);
    float x1 = p[d], x2 = p[d + 32];
    p[d]      = x1 * cs - x2 * sn;
    p[d + 32] = x2 * cs + x1 * sn;
}

// ---------------- attention: sliding-window causal, GQA ----------------
#define QT 128
#define KT 32

__global__ __launch_bounds__(QT)
void attn_kernel(const float* __restrict__ q, const float* __restrict__ k,
                 const float* __restrict__ v, float* __restrict__ out) {
    int bh = blockIdx.y;
    int b = bh / NH, h = bh - b * NH;
    int kh = h / (NH / NKV);
    int q0 = blockIdx.x * QT;
    int tid = threadIdx.x;
    int i = q0 + tid;

    __shared__ float Ks[KT][HD];
    __shared__ float Vs[KT][HD];

    float qr[HD];
    const float* qrow = q + ((size_t)(b * TT + i) * NH + h) * HD;
    #pragma unroll
    for (int d = 0; d < HD; d++) qr[d] = qrow[d] * 0.125f;

    float acc[HD];
    #pragma unroll
    for (int d = 0; d < HD; d++) acc[d] = 0.f;
    float mx = -1e30f, l = 0.f;

    int kmin = q0 - WIN + 1; if (kmin < 0) kmin = 0;
    kmin &= ~(KT - 1);
    int kmax = q0 + QT - 1;

    for (int kt = kmin; kt <= kmax; kt += KT) {
        __syncthreads();
        #pragma unroll
        for (int u = 0; u < 4; u++) {
            int idx = tid + u * QT;
            int r = idx >> 4;
            int c = (idx & 15) * 4;
            const float* kr = k + ((size_t)(b * TT + kt + r) * NKV + kh) * HD;
            const float* vr = v + ((size_t)(b * TT + kt + r) * NKV + kh) * HD;
            *(float4*)&Ks[r][c] = *(const float4*)&kr[c];
            *(float4*)&Vs[r][c] = *(const float4*)&vr[c];
        }
        __syncthreads();

        float s[KT];
        float tm = -1e30f;
        #pragma unroll
        for (int kk = 0; kk < KT; kk++) {
            int j = kt + kk;
            bool ok = (j <= i) && (j > i - WIN);
            float d = 0.f;
            #pragma unroll
            for (int dd = 0; dd < HD; dd++) d += qr[dd] * Ks[kk][dd];
            s[kk] = ok ? d : -1e30f;
            tm = fmaxf(tm, s[kk]);
        }
        if (tm > -9e29f) {
            float nm = fmaxf(mx, tm);
            float corr = __expf(mx - nm);
            l *= corr;
            #pragma unroll
            for (int dd = 0; dd < HD; dd++) acc[dd] *= corr;
            #pragma unroll
            for (int kk = 0; kk < KT; kk++) {
                float p = __expf(s[kk] - nm);
                l += p;
                #pragma unroll
                for (int dd = 0; dd < HD; dd++) acc[dd] += p * Vs[kk][dd];
            }
            mx = nm;
        }
    }
    float inv = 1.f / l;
    float* orow = out + ((size_t)(b * TT + i) * NH + h) * HD;
    #pragma unroll
    for (int d = 0; d < HD; d++) orow[d] = acc[d] * inv;
}

// ---------------- MoE routing ----------------
__global__ void route_kernel(const float* __restrict__ g,
                             const float* __restrict__ gw) {
    int warp = (blockIdx.x * blockDim.x + threadIdx.x) >> 5;
    int lane = threadIdx.x & 31;
    if (warp >= NTOK) return;
    const float* row = g + (size_t)warp * CC;
    float acc[EE] = {};
    for (int kk = lane; kk < CC; kk += 32) {
        float gv = row[kk];
        #pragma unroll
        for (int e = 0; e < EE; e++) acc[e] += gv * gw[kk * EE + e];
    }
    #pragma unroll
    for (int e = 0; e < EE; e++)
        #pragma unroll
        for (int off = 16; off; off >>= 1)
            acc[e] += __shfl_xor_sync(~0u, acc[e], off);
    if (lane == 0) {
        int i0 = 0;
        #pragma unroll
        for (int e = 1; e < EE; e++) if (acc[e] > acc[i0]) i0 = e;
        int i1 = -1;
        #pragma unroll
        for (int e = 0; e < EE; e++)
            if (e != i0 && (i1 < 0 || acc[e] > acc[i1])) i1 = e;
        float m  = acc[i0];
        float p1 = __expf(acc[i1] - m);
        float s  = 1.0f + p1;
        float w0 = 1.0f / s, w1 = p1 / s;
        int pos0 = atomicAdd(&g_counts[i0], 1);
        int pos1 = atomicAdd(&g_counts[i1], 1);
        g_tok[i0 * NTOK + pos0] = warp;
        g_tok[i1 * NTOK + pos1] = warp;
        g_tidx[warp * 2 + 0] = i0; g_tidx[warp * 2 + 1] = i1;
        g_tpos[warp * 2 + 0] = pos0; g_tpos[warp * 2 + 1] = pos1;
        g_twt [warp * 2 + 0] = w0;  g_twt [warp * 2 + 1] = w1;
    }
}

// ---------------- final combine ----------------
__global__ void combine_kernel(float* __restrict__ out) {
    int idx = blockIdx.x * blockDim.x + threadIdx.x;
    int n  = idx >> 8;
    int c4 = idx & 255;
    int e0 = g_tidx[n * 2], e1 = g_tidx[n * 2 + 1];
    int p0 = g_tpos[n * 2], p1 = g_tpos[n * 2 + 1];
    float w0 = g_twt[n * 2], w1 = g_twt[n * 2 + 1];
    float4 h4 = ((const float4*)g_hres)[idx];
    float4 a = ((const float4*)(g_moe + ((size_t)e0 * NTOK + p0) * CC))[c4];
    float4 b = ((const float4*)(g_moe + ((size_t)e1 * NTOK + p1) * CC))[c4];
    float4 o;
    o.x = h4.x + w0 * a.x + w1 * b.x;
    o.y = h4.y + w0 * a.y + w1 * b.y;
    o.z = h4.z + w0 * a.z + w1 * b.z;
    o.w = h4.w + w0 * a.w + w1 * b.w;
    ((float4*)out)[idx] = o;
}

// ---------------- launch ----------------
extern "C" void kernel_launch(void* const* d_in, const int* in_sizes, int n_in,
                              void* d_out, int out_size) {
    const float* x           = (const float*)d_in[0];
    const float* attn_norm_w = (const float*)d_in[1];
    const float* ffn_norm_w  = (const float*)d_in[2];
    const float* wq          = (const float*)d_in[3];
    const float* wk          = (const float*)d_in[4];
    const float* wv          = (const float*)d_in[5];
    const float* wo          = (const float*)d_in[6];
    const float* gate_w      = (const float*)d_in[7];
    const float* w1          = (const float*)d_in[8];
    const float* w2          = (const float*)d_in[9];
    const float* w3          = (const float*)d_in[10];
    float* out = (float*)d_out;

    cudaFuncSetAttribute(mma_gemm<0>, cudaFuncAttributeMaxDynamicSharedMemorySize, SMEMG);
    cudaFuncSetAttribute(mma_gemm<1>, cudaFuncAttributeMaxDynamicSharedMemorySize, SMEMG);

    float *hn, *qb, *kb, *vb, *att, *hres, *gbuf, *hid, *moe;
    int *tok;
    cudaGetSymbolAddress((void**)&hn,   g_hn);
    cudaGetSymbolAddress((void**)&qb,   g_q);
    cudaGetSymbolAddress((void**)&kb,   g_k);
    cudaGetSymbolAddress((void**)&vb,   g_v);
    cudaGetSymbolAddress((void**)&att,  g_att);
    cudaGetSymbolAddress((void**)&hres, g_hres);
    cudaGetSymbolAddress((void**)&gbuf, g_gbuf);
    cudaGetSymbolAddress((void**)&hid,  g_hid);
    cudaGetSymbolAddress((void**)&moe,  g_moe);
    cudaGetSymbolAddress((void**)&tok,  g_tok);

    zero_counts_kernel<<<1, 32>>>();

    rmsnorm_kernel<<<NTOK, 256>>>(x, attn_norm_w, hn);

    // QKV projections (tf32 mma)
    mma_gemm<0><<<dim3(8, 32, 1), 256, SMEMG>>>(hn, nullptr, wq, qb, nullptr,
                                                CC, NH * HD, NTOK, 0, 0, 0);
    mma_gemm<0><<<dim3(2, 32, 1), 256, SMEMG>>>(hn, nullptr, wk, kb, nullptr,
                                                CC, NKV * HD, NTOK, 0, 0, 0);
    mma_gemm<0><<<dim3(2, 32, 1), 256, SMEMG>>>(hn, nullptr, wv, vb, nullptr,
                                                CC, NKV * HD, NTOK, 0, 0, 0);

    rope_kernel<<<(NTOK * NH * 32 + 255) / 256, 256>>>(qb, NH);
    rope_kernel<<<(NTOK * NKV * 32 + 255) / 256, 256>>>(kb, NKV);

    attn_kernel<<<dim3(TT / QT, BB * NH), QT>>>(qb, kb, vb, att);

    // output projection + residual
    mma_gemm<0><<<dim3(8, 32, 1), 256, SMEMG>>>(att, nullptr, wo, hres, x,
                                                CC, CC, NTOK, 0, 0, 0);

    rmsnorm_kernel<<<NTOK, 256>>>(hres, ffn_norm_w, gbuf);

    route_kernel<<<NTOK / 8, 256>>>(gbuf, gate_w);

    // MoE pass 1: hid = g @ w3  (gathered rows)
    mma_gemm<0><<<dim3(FF / 128, NTOK / 128, EE), 256, SMEMG>>>(
        gbuf, tok, w3, hid, nullptr, CC, FF, NTOK,
        0, (size_t)CC * FF, (size_t)NTOK * FF);
    // MoE pass 2: hid = silu(g @ w1) * hid
    mma_gemm<1><<<dim3(FF / 128, NTOK / 128, EE), 256, SMEMG>>>(
        gbuf, tok, w1, hid, nullptr, CC, FF, NTOK,
        0, (size_t)CC * FF, (size_t)NTOK * FF);
    // MoE pass 3: moe = hid @ w2
    mma_gemm<0><<<dim3(CC / 128, NTOK / 128, EE), 256, SMEMG>>>(
        hid, nullptr, w2, moe, nullptr, FF, CC, NTOK,
        (size_t)NTOK * FF, (size_t)FF * CC, (size_t)NTOK * CC);

    combine_kernel<<<(NTOK * CC / 4) / 256, 256>>>(out);
}

// round 4
// speedup vs baseline: 1.8964x; 1.4080x over previous
#include <cuda_runtime.h>
#include <cstdint>

// ---------------- problem constants ----------------
#define BB   4
#define TT   1024
#define CC   1024
#define NH   16
#define NKV  4
#define HD   64
#define EE   8
#define FF   4096
#define WIN  256
#define NTOK (BB*TT)          // 4096
#define EPS  1e-6f

// ---------------- scratch (device globals; no allocs allowed) ----------------
__device__ float g_hn  [(size_t)NTOK*CC];
__device__ float g_q   [(size_t)NTOK*NH*HD];
__device__ float g_k   [(size_t)NTOK*NKV*HD];
__device__ float g_v   [(size_t)NTOK*NKV*HD];
__device__ float g_att [(size_t)NTOK*CC];
__device__ float g_hres[(size_t)NTOK*CC];
__device__ float g_gbuf[(size_t)NTOK*CC];
__device__ int   g_counts[EE];
__device__ int   g_tok [(size_t)EE*NTOK];
__device__ int   g_tidx[(size_t)NTOK*2];
__device__ int   g_tpos[(size_t)NTOK*2];
__device__ float g_twt [(size_t)NTOK*2];
__device__ float g_hid [(size_t)EE*NTOK*FF];
__device__ float g_moe [(size_t)EE*NTOK*CC];

// ---------------- helpers ----------------
__device__ __forceinline__ uint32_t smem_u32(const void* p) {
    uint32_t a;
    asm("{ .reg .u64 t; cvta.to.shared.u64 t, %1; cvt.u32.u64 %0, t; }" : "=r"(a) : "l"(p));
    return a;
}
__device__ __forceinline__ void cp16(uint32_t dst, const void* src) {
    asm volatile("cp.async.cg.shared.global [%0], [%1], 16;" :: "r"(dst), "l"(src));
}
__device__ __forceinline__ void cp_commit() { asm volatile("cp.async.commit_group;" ::: "memory"); }
__device__ __forceinline__ void cp_wait1() { asm volatile("cp.async.wait_group 1;" ::: "memory"); }
__device__ __forceinline__ uint32_t f2tf(float f) {
    uint32_t r; asm("cvt.rna.tf32.f32 %0, %1;" : "=r"(r) : "f"(f)); return r;
}
__device__ __forceinline__ void mma8(float* c, const uint32_t* a, const uint32_t* b) {
    asm volatile("mma.sync.aligned.m16n8k8.row.col.f32.tf32.tf32.f32 "
                 "{%0,%1,%2,%3}, {%4,%5,%6,%7}, {%8,%9}, {%0,%1,%2,%3};"
                 : "+f"(c[0]), "+f"(c[1]), "+f"(c[2]), "+f"(c[3])
                 : "r"(a[0]), "r"(a[1]), "r"(a[2]), "r"(a[3]), "r"(b[0]), "r"(b[1]));
}

// ---------------- mma.sync tf32 GEMM core ----------------
// block tile 128x128x32, 8 warps (4m x 2n), warp tile 32x64, 3-stage cp.async
#define NSTG 3
#define ASTRIDE 36      // floats per A smem row (128 rows)
#define BSTRIDE 136     // floats per B smem row (32 rows)
#define ASZ (128*ASTRIDE)
#define BSZ (32*BSTRIDE)
#define SMEMG (NSTG*(ASZ+BSZ)*4)   // 107520 bytes

// EPI 0: C = acc (+res if res!=null) ; EPI 1: C = silu(acc) * C
template<int EPI>
__device__ __forceinline__ void gemm_body(
    const float* __restrict__ A, const int* __restrict__ list, int cnt, int m0,
    const float* __restrict__ W, float* __restrict__ C, const float* __restrict__ res,
    int K, int Nw, int nloc, float* smf)
{
    float* Abuf[NSTG];
    float* Bbuf[NSTG];
    #pragma unroll
    for (int s = 0; s < NSTG; s++) {
        Abuf[s] = smf + s * ASZ;
        Bbuf[s] = smf + NSTG * ASZ + s * BSZ;
    }

    int tid = threadIdx.x;
    int lane = tid & 31, warp = tid >> 5;
    int wm = warp & 3, wn = warp >> 2;

    // ---- load geometry ----
    int ar = tid >> 1;              // A row 0..127
    int af = (tid & 1) * 4;         // A float4 slot base (0 or 4)
    const float* arow;
    {
        int grow = m0 + ar;
        if (list) { int g2 = (grow < cnt) ? grow : 0; arow = A + (size_t)list[g2] * K; }
        else      arow = A + (size_t)grow * K;
    }
    int bk = tid >> 3;              // B k-row 0..31
    int bf = tid & 7;               // B float4 slot base
    const float* brow = W + (size_t)bk * Nw + nloc + bf * 4;

    uint32_t aD[NSTG], bD[NSTG];
    #pragma unroll
    for (int p = 0; p < NSTG; p++) {
        aD[p] = smem_u32(Abuf[p]) + (ar * ASTRIDE + af * 4) * 4;
        bD[p] = smem_u32(Bbuf[p]) + (bk * BSTRIDE + bf * 4) * 4;
    }

    auto load_chunk = [&](int ci, int p) {
        const float* as = arow + ci * 32 + af * 4;
        #pragma unroll
        for (int j = 0; j < 4; j++) cp16(aD[p] + j * 16, as + j * 4);
        const float* bs = brow + (size_t)ci * 32 * Nw;
        #pragma unroll
        for (int j = 0; j < 4; j++) cp16(bD[p] + j * 128, bs + j * 32);
    };

    float acc[2][8][4];
    #pragma unroll
    for (int mi = 0; mi < 2; mi++)
        #pragma unroll
        for (int ni = 0; ni < 8; ni++)
            #pragma unroll
            for (int q = 0; q < 4; q++) acc[mi][ni][q] = 0.f;

    int lr = lane >> 2, lc = lane & 3;

    auto compute = [&](int p) {
        const float* Am = Abuf[p];
        const float* Bm = Bbuf[p];
        #pragma unroll
        for (int kk = 0; kk < 4; kk++) {
            int kb = kk * 8;
            uint32_t a[2][4], b[8][2];
            #pragma unroll
            for (int mi = 0; mi < 2; mi++) {
                const float* ap = Am + (wm * 32 + mi * 16 + lr) * ASTRIDE + kb + lc;
                a[mi][0] = f2tf(ap[0]);
                a[mi][1] = f2tf(ap[8 * ASTRIDE]);
                a[mi][2] = f2tf(ap[4]);
                a[mi][3] = f2tf(ap[8 * ASTRIDE + 4]);
            }
            #pragma unroll
            for (int ni = 0; ni < 8; ni++) {
                const float* bp = Bm + (kb + lc) * BSTRIDE + wn * 64 + ni * 8 + lr;
                b[ni][0] = f2tf(bp[0]);
                b[ni][1] = f2tf(bp[4 * BSTRIDE]);
            }
            #pragma unroll
            for (int mi = 0; mi < 2; mi++)
                #pragma unroll
                for (int ni = 0; ni < 8; ni++)
                    mma8(acc[mi][ni], a[mi], b[ni]);
        }
    };

    int NC = K / 32;
    // prologue: stages 0 .. NSTG-2
    load_chunk(0, 0); cp_commit();
    load_chunk(1, 1); cp_commit();
    for (int i = 0; i < NC; i++) {
        cp_wait1();                  // chunk i resident (in-order retirement)
        __syncthreads();
        int nx = i + NSTG - 1;
        if (nx < NC) load_chunk(nx, nx % NSTG);   // overlaps with compute below
        cp_commit();                 // empty groups keep the count consistent
        compute(i % NSTG);
    }

    // ---- epilogue ----
    int tc = (lane & 3) * 2;
    #pragma unroll
    for (int mi = 0; mi < 2; mi++) {
        #pragma unroll
        for (int half = 0; half < 2; half++) {
            int m = m0 + wm * 32 + mi * 16 + half * 8 + lr;
            if (m < cnt) {
                float* crow = C + (size_t)m * Nw + nloc + wn * 64;
                #pragma unroll
                for (int ni = 0; ni < 8; ni++) {
                    float c0 = acc[mi][ni][half * 2 + 0];
                    float c1 = acc[mi][ni][half * 2 + 1];
                    float2* cp2 = (float2*)(crow + ni * 8 + tc);
                    if (EPI == 0) {
                        if (res) {
                            const float2 rr = *(const float2*)(res + (size_t)m * Nw + nloc + wn * 64 + ni * 8 + tc);
                            c0 += rr.x; c1 += rr.y;
                        }
                        float2 v; v.x = c0; v.y = c1;
                        *cp2 = v;
                    } else {
                        float2 e = *cp2;
                        float2 v;
                        v.x = c0 / (1.f + __expf(-c0)) * e.x;
                        v.y = c1 / (1.f + __expf(-c1)) * e.y;
                        *cp2 = v;
                    }
                }
            }
        }
    }
}

// generic GEMM kernel (dense or gathered / per-expert via blockIdx.z)
template<int EPI>
__global__ __launch_bounds__(256, 2)
void mma_gemm(const float* __restrict__ Abase, const int* __restrict__ glist,
              const float* __restrict__ Wbase, float* __restrict__ Cbase,
              const float* __restrict__ res, int K, int N, int Mtot,
              size_t aStrE, size_t wStrE, size_t cStrE)
{
    int z = blockIdx.z;
    int cnt = (gridDim.z > 1) ? g_counts[z] : Mtot;
    int m0 = blockIdx.y * 128;
    if (m0 >= cnt) return;
    extern __shared__ float smf[];
    gemm_body<EPI>(Abase + aStrE * z,
                   glist ? (glist + (size_t)z * NTOK) : (const int*)0,
                   cnt, m0,
                   Wbase + wStrE * z, Cbase + cStrE * z, res,
                   K, N, blockIdx.x * 128, smf);
}

// fused QKV: one launch covers wq (8 n-blocks), wk (2), wv (2)
__global__ __launch_bounds__(256, 2)
void qkv_gemm(const float* __restrict__ hn,
              const float* __restrict__ wq, const float* __restrict__ wk,
              const float* __restrict__ wv)
{
    extern __shared__ float smf[];
    int m0 = blockIdx.y * 128;
    int nb = blockIdx.x;
    const float* W; float* O; int Nw, nloc;
    if (nb < 8)       { W = wq; O = g_q; Nw = NH * HD;  nloc = nb * 128; }
    else if (nb < 10) { W = wk; O = g_k; Nw = NKV * HD; nloc = (nb - 8) * 128; }
    else              { W = wv; O = g_v; Nw = NKV * HD; nloc = (nb - 10) * 128; }
    gemm_body<0>(hn, (const int*)0, NTOK, m0, W, O, (const float*)0, CC, Nw, nloc, smf);
}

// ---------------- small kernels ----------------
__global__ void zero_counts_kernel() {
    if (threadIdx.x < EE) g_counts[threadIdx.x] = 0;
}

__global__ void rmsnorm_kernel(const float* __restrict__ x,
                               const float* __restrict__ w,
                               float* __restrict__ o) {
    int row = blockIdx.x;
    const float* xr = x + (size_t)row * CC;
    __shared__ float red[8];
    float s = 0.f;
    for (int c = threadIdx.x; c < CC; c += 256) { float v = xr[c]; s += v * v; }
    #pragma unroll
    for (int off = 16; off; off >>= 1) s += __shfl_xor_sync(~0u, s, off);
    if ((threadIdx.x & 31) == 0) red[threadIdx.x >> 5] = s;
    __syncthreads();
    if (threadIdx.x < 8) {
        float t = red[threadIdx.x];
        #pragma unroll
        for (int off = 4; off; off >>= 1) t += __shfl_xor_sync(0xff, t, off);
        if (threadIdx.x == 0) red[0] = t;
    }
    __syncthreads();
    float inv = rsqrtf(red[0] * (1.0f / CC) + EPS);
    for (int c = threadIdx.x; c < CC; c += 256)
        o[(size_t)row * CC + c] = xr[c] * inv * w[c];
}

__global__ void rope_kernel(float* __restrict__ t, int nh) {
    int idx = blockIdx.x * blockDim.x + threadIdx.x;
    int total = NTOK * nh * 32;
    if (idx >= total) return;
    int n = idx / (nh * 32);
    int r = idx - n * (nh * 32);
    int h = r >> 5;
    int d = r & 31;
    int pos = n & (TT - 1);
    float* p = t + ((size_t)n * nh + h) * HD;
    float fr  = __powf(10000.0f, -(float)d * (1.0f / 32.0f));
    float ang = (float)pos * fr;
    float cs = cosf(ang), sn = sinf(ang);
    float x1 = p[d], x2 = p[d + 32];
    p[d]      = x1 * cs - x2 * sn;
    p[d + 32] = x2 * cs + x1 * sn;
}

// ---------------- attention: sliding-window causal, GQA ----------------
#define QT 128
#define KT 32

__global__ __launch_bounds__(QT)
void attn_kernel(const float* __restrict__ q, const float* __restrict__ k,
                 const float* __restrict__ v, float* __restrict__ out) {
    int bh = blockIdx.y;
    int b = bh / NH, h = bh - b * NH;
    int kh = h / (NH / NKV);
    int q0 = blockIdx.x * QT;
    int tid = threadIdx.x;
    int i = q0 + tid;

    __shared__ float Ks[KT][HD];
    __shared__ float Vs[KT][HD];

    float qr[HD];
    const float* qrow = q + ((size_t)(b * TT + i) * NH + h) * HD;
    #pragma unroll
    for (int d = 0; d < HD; d++) qr[d] = qrow[d] * 0.125f;

    float acc[HD];
    #pragma unroll
    for (int d = 0; d < HD; d++) acc[d] = 0.f;
    float mx = -1e30f, l = 0.f;

    int kmin = q0 - WIN + 1; if (kmin < 0) kmin = 0;
    kmin &= ~(KT - 1);
    int kmax = q0 + QT - 1;

    for (int kt = kmin; kt <= kmax; kt += KT) {
        __syncthreads();
        #pragma unroll
        for (int u = 0; u < 4; u++) {
            int idx = tid + u * QT;
            int r = idx >> 4;
            int c = (idx & 15) * 4;
            const float* kr = k + ((size_t)(b * TT + kt + r) * NKV + kh) * HD;
            const float* vr = v + ((size_t)(b * TT + kt + r) * NKV + kh) * HD;
            *(float4*)&Ks[r][c] = *(const float4*)&kr[c];
            *(float4*)&Vs[r][c] = *(const float4*)&vr[c];
        }
        __syncthreads();

        float s[KT];
        float tm = -1e30f;
        #pragma unroll
        for (int kk = 0; kk < KT; kk++) {
            int j = kt + kk;
            bool ok = (j <= i) && (j > i - WIN);
            float d = 0.f;
            #pragma unroll
            for (int dd = 0; dd < HD; dd++) d += qr[dd] * Ks[kk][dd];
            s[kk] = ok ? d : -1e30f;
            tm = fmaxf(tm, s[kk]);
        }
        if (tm > -9e29f) {
            float nm = fmaxf(mx, tm);
            float corr = __expf(mx - nm);
            l *= corr;
            #pragma unroll
            for (int dd = 0; dd < HD; dd++) acc[dd] *= corr;
            #pragma unroll
            for (int kk = 0; kk < KT; kk++) {
                float p = __expf(s[kk] - nm);
                l += p;
                #pragma unroll
                for (int dd = 0; dd < HD; dd++) acc[dd] += p * Vs[kk][dd];
            }
            mx = nm;
        }
    }
    float inv = 1.f / l;
    float* orow = out + ((size_t)(b * TT + i) * NH + h) * HD;
    #pragma unroll
    for (int d = 0; d < HD; d++) orow[d] = acc[d] * inv;
}

// ---------------- MoE routing ----------------
__global__ void route_kernel(const float* __restrict__ g,
                             const float* __restrict__ gw) {
    int warp = (blockIdx.x * blockDim.x + threadIdx.x) >> 5;
    int lane = threadIdx.x & 31;
    if (warp >= NTOK) return;
    const float* row = g + (size_t)warp * CC;
    float acc[EE] = {};
    for (int kk = lane; kk < CC; kk += 32) {
        float gv = row[kk];
        #pragma unroll
        for (int e = 0; e < EE; e++) acc[e] += gv * gw[kk * EE + e];
    }
    #pragma unroll
    for (int e = 0; e < EE; e++)
        #pragma unroll
        for (int off = 16; off; off >>= 1)
            acc[e] += __shfl_xor_sync(~0u, acc[e], off);
    if (lane == 0) {
        int i0 = 0;
        #pragma unroll
        for (int e = 1; e < EE; e++) if (acc[e] > acc[i0]) i0 = e;
        int i1 = -1;
        #pragma unroll
        for (int e = 0; e < EE; e++)
            if (e != i0 && (i1 < 0 || acc[e] > acc[i1])) i1 = e;
        float m  = acc[i0];
        float p1 = __expf(acc[i1] - m);
        float s  = 1.0f + p1;
        float w0 = 1.0f / s, w1 = p1 / s;
        int pos0 = atomicAdd(&g_counts[i0], 1);
        int pos1 = atomicAdd(&g_counts[i1], 1);
        g_tok[i0 * NTOK + pos0] = warp;
        g_tok[i1 * NTOK + pos1] = warp;
        g_tidx[warp * 2 + 0] = i0; g_tidx[warp * 2 + 1] = i1;
        g_tpos[warp * 2 + 0] = pos0; g_tpos[warp * 2 + 1] = pos1;
        g_twt [warp * 2 + 0] = w0;  g_twt [warp * 2 + 1] = w1;
    }
}

// ---------------- final combine ----------------
__global__ void combine_kernel(float* __restrict__ out) {
    int idx = blockIdx.x * blockDim.x + threadIdx.x;
    int n  = idx >> 8;
    int c4 = idx & 255;
    int e0 = g_tidx[n * 2], e1 = g_tidx[n * 2 + 1];
    int p0 = g_tpos[n * 2], p1 = g_tpos[n * 2 + 1];
    float w0 = g_twt[n * 2], w1 = g_twt[n * 2 + 1];
    float4 h4 = ((const float4*)g_hres)[idx];
    float4 a = ((const float4*)(g_moe + ((size_t)e0 * NTOK + p0) * CC))[c4];
    float4 b = ((const float4*)(g_moe + ((size_t)e1 * NTOK + p1) * CC))[c4];
    float4 o;
    o.x = h4.x + w0 * a.x + w1 * b.x;
    o.y = h4.y + w0 * a.y + w1 * b.y;
    o.z = h4.z + w0 * a.z + w1 * b.z;
    o.w = h4.w + w0 * a.w + w1 * b.w;
    ((float4*)out)[idx] = o;
}

// ---------------- launch ----------------
extern "C" void kernel_launch(void* const* d_in, const int* in_sizes, int n_in,
                              void* d_out, int out_size) {
    const float* x           = (const float*)d_in[0];
    const float* attn_norm_w = (const float*)d_in[1];
    const float* ffn_norm_w  = (const float*)d_in[2];
    const float* wq          = (const float*)d_in[3];
    const float* wk          = (const float*)d_in[4];
    const float* wv          = (const float*)d_in[5];
    const float* wo          = (const float*)d_in[6];
    const float* gate_w      = (const float*)d_in[7];
    const float* w1          = (const float*)d_in[8];
    const float* w2          = (const float*)d_in[9];
    const float* w3          = (const float*)d_in[10];
    float* out = (float*)d_out;

    cudaFuncSetAttribute(mma_gemm<0>, cudaFuncAttributeMaxDynamicSharedMemorySize, SMEMG);
    cudaFuncSetAttribute(mma_gemm<1>, cudaFuncAttributeMaxDynamicSharedMemorySize, SMEMG);
    cudaFuncSetAttribute(qkv_gemm,    cudaFuncAttributeMaxDynamicSharedMemorySize, SMEMG);

    float *hn, *qb, *kb, *vb, *att, *hres, *gbuf, *hid, *moe;
    int *tok;
    cudaGetSymbolAddress((void**)&hn,   g_hn);
    cudaGetSymbolAddress((void**)&qb,   g_q);
    cudaGetSymbolAddress((void**)&kb,   g_k);
    cudaGetSymbolAddress((void**)&vb,   g_v);
    cudaGetSymbolAddress((void**)&att,  g_att);
    cudaGetSymbolAddress((void**)&hres, g_hres);
    cudaGetSymbolAddress((void**)&gbuf, g_gbuf);
    cudaGetSymbolAddress((void**)&hid,  g_hid);
    cudaGetSymbolAddress((void**)&moe,  g_moe);
    cudaGetSymbolAddress((void**)&tok,  g_tok);

    zero_counts_kernel<<<1, 32>>>();

    rmsnorm_kernel<<<NTOK, 256>>>(x, attn_norm_w, hn);

    // fused QKV projections
    qkv_gemm<<<dim3(12, 32), 256, SMEMG>>>(hn, wq, wk, wv);

    rope_kernel<<<(NTOK * NH * 32 + 255) / 256, 256>>>(qb, NH);
    rope_kernel<<<(NTOK * NKV * 32 + 255) / 256, 256>>>(kb, NKV);

    attn_kernel<<<dim3(TT / QT, BB * NH), QT>>>(qb, kb, vb, att);

    // output projection + residual
    mma_gemm<0><<<dim3(8, 32, 1), 256, SMEMG>>>(att, nullptr, wo, hres, x,
                                                CC, CC, NTOK, 0, 0, 0);

    rmsnorm_kernel<<<NTOK, 256>>>(hres, ffn_norm_w, gbuf);

    route_kernel<<<NTOK / 8, 256>>>(gbuf, gate_w);

    // MoE pass 1: hid = g @ w3  (gathered rows)
    mma_gemm<0><<<dim3(FF / 128, NTOK / 128, EE), 256, SMEMG>>>(
        gbuf, tok, w3, hid, nullptr, CC, FF, NTOK,
        0, (size_t)CC * FF, (size_t)NTOK * FF);
    // MoE pass 2: hid = silu(g @ w1) * hid
    mma_gemm<1><<<dim3(FF / 128, NTOK / 128, EE), 256, SMEMG>>>(
        gbuf, tok, w1, hid, nullptr, CC, FF, NTOK,
        0, (size_t)CC * FF, (size_t)NTOK * FF);
    // MoE pass 3: moe = hid @ w2
    mma_gemm<0><<<dim3(CC / 128, NTOK / 128, EE), 256, SMEMG>>>(
        hid, nullptr, w2, moe, nullptr, FF, CC, NTOK,
        (size_t)NTOK * FF, (size_t)FF * CC, (size_t)NTOK * CC);

    combine_kernel<<<(NTOK * CC / 4) / 256, 256>>>(out);
}

// round 5
// speedup vs baseline: 1.9652x; 1.0363x over previous
#include <cuda_runtime.h>
#include <cuda_bf16.h>
#include <cstdint>

// ---------------- problem constants ----------------
#define BB   4
#define TT   1024
#define CC   1024
#define NH   16
#define NKV  4
#define HD   64
#define EE   8
#define FF   4096
#define WIN  256
#define NTOK (BB*TT)          // 4096
#define EPS  1e-6f

// ---------------- scratch (device globals; no allocs allowed) ----------------
__device__ float g_hn  [(size_t)NTOK*CC];
__device__ float g_q   [(size_t)NTOK*NH*HD];
__device__ float g_k   [(size_t)NTOK*NKV*HD];
__device__ float g_v   [(size_t)NTOK*NKV*HD];
__device__ float g_att [(size_t)NTOK*CC];
__device__ float g_hres[(size_t)NTOK*CC];
__device__ float g_gbuf[(size_t)NTOK*CC];
__device__ int   g_counts[EE];
__device__ int   g_tok [(size_t)EE*NTOK];
__device__ int   g_tidx[(size_t)NTOK*2];
__device__ int   g_tpos[(size_t)NTOK*2];
__device__ float g_twt [(size_t)NTOK*2];
__device__ float g_moe [(size_t)EE*NTOK*CC];
// bf16 buffers (as ushort to keep trivial init)
__device__ unsigned short g_gb16 [(size_t)NTOK*CC];
__device__ unsigned short g_hid16[(size_t)EE*NTOK*FF];
__device__ unsigned short g_w1t  [(size_t)EE*CC*FF];    // [e][FF][CC]
__device__ unsigned short g_w3t  [(size_t)EE*CC*FF];
__device__ unsigned short g_w2t  [(size_t)EE*FF*CC];    // [e][CC][FF]

// ---------------- helpers ----------------
__device__ __forceinline__ uint32_t smem_u32(const void* p) {
    uint32_t a;
    asm("{ .reg .u64 t; cvta.to.shared.u64 t, %1; cvt.u32.u64 %0, t; }" : "=r"(a) : "l"(p));
    return a;
}
__device__ __forceinline__ void cp16(uint32_t dst, const void* src) {
    asm volatile("cp.async.cg.shared.global [%0], [%1], 16;" :: "r"(dst), "l"(src));
}
__device__ __forceinline__ void cp_commit() { asm volatile("cp.async.commit_group;" ::: "memory"); }
__device__ __forceinline__ void cp_wait1() { asm volatile("cp.async.wait_group 1;" ::: "memory"); }
__device__ __forceinline__ void cp_wait2() { asm volatile("cp.async.wait_group 2;" ::: "memory"); }
__device__ __forceinline__ uint32_t f2tf(float f) {
    uint32_t r; asm("cvt.rna.tf32.f32 %0, %1;" : "=r"(r) : "f"(f)); return r;
}
__device__ __forceinline__ void mma8(float* c, const uint32_t* a, const uint32_t* b) {
    asm volatile("mma.sync.aligned.m16n8k8.row.col.f32.tf32.tf32.f32 "
                 "{%0,%1,%2,%3}, {%4,%5,%6,%7}, {%8,%9}, {%0,%1,%2,%3};"
                 : "+f"(c[0]), "+f"(c[1]), "+f"(c[2]), "+f"(c[3])
                 : "r"(a[0]), "r"(a[1]), "r"(a[2]), "r"(a[3]), "r"(b[0]), "r"(b[1]));
}
__device__ __forceinline__ void mma16(float* c, const uint32_t* a, const uint32_t* b) {
    asm volatile("mma.sync.aligned.m16n8k16.row.col.f32.bf16.bf16.f32 "
                 "{%0,%1,%2,%3}, {%4,%5,%6,%7}, {%8,%9}, {%0,%1,%2,%3};"
                 : "+f"(c[0]), "+f"(c[1]), "+f"(c[2]), "+f"(c[3])
                 : "r"(a[0]), "r"(a[1]), "r"(a[2]), "r"(a[3]), "r"(b[0]), "r"(b[1]));
}

// ================= tf32 GEMM core (attention path) =================
// block tile 128x128x32, 8 warps (4m x 2n), warp tile 32x64, 3-stage cp.async
#define NSTG 3
#define ASTRIDE 36
#define BSTRIDE 136
#define ASZ (128*ASTRIDE)
#define BSZ (32*BSTRIDE)
#define SMEMG (NSTG*(ASZ+BSZ)*4)   // 107520 bytes

__device__ __forceinline__ void gemm_body_tf32(
    const float* __restrict__ A, int m0,
    const float* __restrict__ W, float* __restrict__ C, const float* __restrict__ res,
    int K, int Nw, int nloc, float* smf)
{
    float* Abuf[NSTG];
    float* Bbuf[NSTG];
    #pragma unroll
    for (int s = 0; s < NSTG; s++) {
        Abuf[s] = smf + s * ASZ;
        Bbuf[s] = smf + NSTG * ASZ + s * BSZ;
    }
    int tid = threadIdx.x;
    int lane = tid & 31, warp = tid >> 5;
    int wm = warp & 3, wn = warp >> 2;

    int ar = tid >> 1;
    int af = (tid & 1) * 4;
    const float* arow = A + (size_t)(m0 + ar) * K;
    int bk = tid >> 3;
    int bf = tid & 7;
    const float* brow = W + (size_t)bk * Nw + nloc + bf * 4;

    uint32_t aD[NSTG], bD[NSTG];
    #pragma unroll
    for (int p = 0; p < NSTG; p++) {
        aD[p] = smem_u32(Abuf[p]) + (ar * ASTRIDE + af * 4) * 4;
        bD[p] = smem_u32(Bbuf[p]) + (bk * BSTRIDE + bf * 4) * 4;
    }

    auto load_chunk = [&](int ci, int p) {
        const float* as = arow + ci * 32 + af * 4;
        #pragma unroll
        for (int j = 0; j < 4; j++) cp16(aD[p] + j * 16, as + j * 4);
        const float* bs = brow + (size_t)ci * 32 * Nw;
        #pragma unroll
        for (int j = 0; j < 4; j++) cp16(bD[p] + j * 128, bs + j * 32);
    };

    float acc[2][8][4];
    #pragma unroll
    for (int mi = 0; mi < 2; mi++)
        #pragma unroll
        for (int ni = 0; ni < 8; ni++)
            #pragma unroll
            for (int q = 0; q < 4; q++) acc[mi][ni][q] = 0.f;

    int lr = lane >> 2, lc = lane & 3;

    auto compute = [&](int p) {
        const float* Am = Abuf[p];
        const float* Bm = Bbuf[p];
        #pragma unroll
        for (int kk = 0; kk < 4; kk++) {
            int kb = kk * 8;
            uint32_t a[2][4], b[8][2];
            #pragma unroll
            for (int mi = 0; mi < 2; mi++) {
                const float* ap = Am + (wm * 32 + mi * 16 + lr) * ASTRIDE + kb + lc;
                a[mi][0] = f2tf(ap[0]);
                a[mi][1] = f2tf(ap[8 * ASTRIDE]);
                a[mi][2] = f2tf(ap[4]);
                a[mi][3] = f2tf(ap[8 * ASTRIDE + 4]);
            }
            #pragma unroll
            for (int ni = 0; ni < 8; ni++) {
                const float* bp = Bm + (kb + lc) * BSTRIDE + wn * 64 + ni * 8 + lr;
                b[ni][0] = f2tf(bp[0]);
                b[ni][1] = f2tf(bp[4 * BSTRIDE]);
            }
            #pragma unroll
            for (int mi = 0; mi < 2; mi++)
                #pragma unroll
                for (int ni = 0; ni < 8; ni++)
                    mma8(acc[mi][ni], a[mi], b[ni]);
        }
    };

    int NC = K / 32;
    load_chunk(0, 0); cp_commit();
    load_chunk(1, 1); cp_commit();
    for (int i = 0; i < NC; i++) {
        cp_wait1();
        __syncthreads();
        int nx = i + NSTG - 1;
        if (nx < NC) load_chunk(nx, nx % NSTG);
        cp_commit();
        compute(i % NSTG);
    }

    int tc = (lane & 3) * 2;
    #pragma unroll
    for (int mi = 0; mi < 2; mi++) {
        #pragma unroll
        for (int half = 0; half < 2; half++) {
            int m = m0 + wm * 32 + mi * 16 + half * 8 + lr;
            float* crow = C + (size_t)m * Nw + nloc + wn * 64;
            #pragma unroll
            for (int ni = 0; ni < 8; ni++) {
                float c0 = acc[mi][ni][half * 2 + 0];
                float c1 = acc[mi][ni][half * 2 + 1];
                if (res) {
                    const float2 rr = *(const float2*)(res + (size_t)m * Nw + nloc + wn * 64 + ni * 8 + tc);
                    c0 += rr.x; c1 += rr.y;
                }
                float2 v; v.x = c0; v.y = c1;
                *(float2*)(crow + ni * 8 + tc) = v;
            }
        }
    }
}

__global__ __launch_bounds__(256, 2)
void wo_gemm(const float* __restrict__ A, const float* __restrict__ W,
             float* __restrict__ C, const float* __restrict__ res)
{
    extern __shared__ float smf[];
    gemm_body_tf32(A, blockIdx.y * 128, W, C, res, CC, CC, blockIdx.x * 128, smf);
}

__global__ __launch_bounds__(256, 2)
void qkv_gemm(const float* __restrict__ hn,
              const float* __restrict__ wq, const float* __restrict__ wk,
              const float* __restrict__ wv)
{
    extern __shared__ float smf[];
    int m0 = blockIdx.y * 128;
    int nb = blockIdx.x;
    const float* W; float* O; int Nw, nloc;
    if (nb < 8)       { W = wq; O = g_q; Nw = NH * HD;  nloc = nb * 128; }
    else if (nb < 10) { W = wk; O = g_k; Nw = NKV * HD; nloc = (nb - 8) * 128; }
    else              { W = wv; O = g_v; Nw = NKV * HD; nloc = (nb - 10) * 128; }
    gemm_body_tf32(hn, m0, W, O, (const float*)0, CC, Nw, nloc, smf);
}

// ================= bf16 GEMM core (MoE path) =================
// block tile 128x128x32, 8 warps (4m x 2n), warp tile 32x64, 4-stage cp.async
// A smem [128][40] halves (80B rows), B smem [128 n][40] halves (B pre-transposed [N][K] in gmem)
#define HST 40
#define HTILE_B (128*HST*2)        // 10240 bytes per tile
#define NS16 4
#define SMEM16 (NS16*2*HTILE_B)    // 81920 bytes

// EPI 0: fp32 C = acc ; EPI 1: bf16 C = acc ; EPI 2: bf16 C = silu(acc) * C
template<int EPI>
__global__ __launch_bounds__(256, 2)
void bf16_gemm(const unsigned short* __restrict__ Abase, const int* __restrict__ glist,
               const unsigned short* __restrict__ Wtbase, void* __restrict__ Cbase,
               int K, int N, size_t aStrE, size_t wStrE, size_t cStrE)
{
    int z = blockIdx.z;
    int cnt = g_counts[z];
    int m0 = blockIdx.y * 128;
    if (m0 >= cnt) return;
    int n0 = blockIdx.x * 128;

    const unsigned short* A  = Abase + aStrE * z;
    const unsigned short* Wt = Wtbase + wStrE * z;
    const int* list = glist ? (glist + (size_t)z * NTOK) : (const int*)0;

    extern __shared__ char smraw[];
    int tid = threadIdx.x, lane = tid & 31, warp = tid >> 5;
    int wm = warp & 3, wn = warp >> 2;

    // load geometry: thread -> row (0..127), 2 x 16B slots
    int row = tid >> 1, sl = (tid & 1) * 2;
    const unsigned short* arow;
    {
        int grow = m0 + row;
        if (list) { int g2 = (grow < cnt) ? grow : 0; arow = A + (size_t)list[g2] * K; }
        else      arow = A + (size_t)grow * K;
    }
    const unsigned short* brow = Wt + (size_t)(n0 + row) * K;

    uint32_t sbase = smem_u32(smraw);
    uint32_t aD[NS16], bD[NS16];
    #pragma unroll
    for (int s = 0; s < NS16; s++) {
        aD[s] = sbase + s * (2 * HTILE_B) + row * 80 + sl * 16;
        bD[s] = aD[s] + HTILE_B;
    }

    auto load_chunk = [&](int ci, int p) {
        const unsigned short* as = arow + ci * 32 + sl * 8;
        cp16(aD[p], as); cp16(aD[p] + 16, as + 8);
        const unsigned short* bs = brow + ci * 32 + sl * 8;
        cp16(bD[p], bs); cp16(bD[p] + 16, bs + 8);
    };

    float acc[2][8][4];
    #pragma unroll
    for (int mi = 0; mi < 2; mi++)
        #pragma unroll
        for (int ni = 0; ni < 8; ni++)
            #pragma unroll
            for (int q = 0; q < 4; q++) acc[mi][ni][q] = 0.f;

    int lr = lane >> 2, lc = lane & 3;

    auto compute = [&](int p) {
        const char* Am = smraw + p * (2 * HTILE_B);
        const char* Bm = Am + HTILE_B;
        #pragma unroll
        for (int kk = 0; kk < 2; kk++) {
            int kc = kk * 32 + lc * 4;            // byte offset of k-fragment
            uint32_t a[2][4], b[8][2];
            #pragma unroll
            for (int mi = 0; mi < 2; mi++) {
                const char* ap = Am + (wm * 32 + mi * 16 + lr) * 80 + kc;
                a[mi][0] = *(const uint32_t*)(ap);
                a[mi][1] = *(const uint32_t*)(ap + 8 * 80);
                a[mi][2] = *(const uint32_t*)(ap + 16);
                a[mi][3] = *(const uint32_t*)(ap + 8 * 80 + 16);
            }
            #pragma unroll
            for (int ni = 0; ni < 8; ni++) {
                const char* bp = Bm + (wn * 64 + ni * 8 + lr) * 80 + kc;
                b[ni][0] = *(const uint32_t*)(bp);
                b[ni][1] = *(const uint32_t*)(bp + 16);
            }
            #pragma unroll
            for (int mi = 0; mi < 2; mi++)
                #pragma unroll
                for (int ni = 0; ni < 8; ni++)
                    mma16(acc[mi][ni], a[mi], b[ni]);
        }
    };

    int NC = K / 32;
    load_chunk(0, 0); cp_commit();
    load_chunk(1, 1); cp_commit();
    load_chunk(2, 2); cp_commit();
    for (int i = 0; i < NC; i++) {
        cp_wait2();
        __syncthreads();
        int nx = i + NS16 - 1;
        if (nx < NC) load_chunk(nx, nx % NS16);
        cp_commit();
        compute(i % NS16);
    }

    // epilogue
    #pragma unroll
    for (int mi = 0; mi < 2; mi++) {
        #pragma unroll
        for (int half = 0; half < 2; half++) {
            int m = m0 + wm * 32 + mi * 16 + half * 8 + lr;
            if (m < cnt) {
                int col = n0 + wn * 64;
                #pragma unroll
                for (int ni = 0; ni < 8; ni++) {
                    float c0 = acc[mi][ni][half * 2 + 0];
                    float c1 = acc[mi][ni][half * 2 + 1];
                    size_t off = (size_t)m * N + col + ni * 8 + lc * 2;
                    if (EPI == 0) {
                        float* C = (float*)Cbase + cStrE * z;
                        float2 v; v.x = c0; v.y = c1;
                        *(float2*)(C + off) = v;
                    } else if (EPI == 1) {
                        __nv_bfloat16* C = (__nv_bfloat16*)Cbase + cStrE * z;
                        *(__nv_bfloat162*)(C + off) =
                            __nv_bfloat162(__float2bfloat16_rn(c0), __float2bfloat16_rn(c1));
                    } else {
                        __nv_bfloat16* C = (__nv_bfloat16*)Cbase + cStrE * z;
                        __nv_bfloat162 e = *(__nv_bfloat162*)(C + off);
                        float v0 = c0 / (1.f + __expf(-c0)) * __bfloat162float(e.x);
                        float v1 = c1 / (1.f + __expf(-c1)) * __bfloat162float(e.y);
                        *(__nv_bfloat162*)(C + off) =
                            __nv_bfloat162(__float2bfloat16_rn(v0), __float2bfloat16_rn(v1));
                    }
                }
            }
        }
    }
}

// ---------------- weight transpose+convert: [K][N] f32 -> [N][K] bf16 ----------------
__global__ void transpose_bf16(const float* __restrict__ src, unsigned short* __restrict__ dst,
                               int K, int N) {
    __shared__ float t[32][33];
    const float* s = src + (size_t)blockIdx.z * K * N;
    unsigned short* d = dst + (size_t)blockIdx.z * K * N;
    int k0 = blockIdx.y * 32, n0 = blockIdx.x * 32;
    int tx = threadIdx.x & 31, ty = threadIdx.x >> 5;
    #pragma unroll
    for (int p = 0; p < 4; p++)
        t[ty + p * 8][tx] = s[(size_t)(k0 + ty + p * 8) * N + n0 + tx];
    __syncthreads();
    #pragma unroll
    for (int p = 0; p < 4; p++) {
        __nv_bfloat16 v = __float2bfloat16_rn(t[tx][ty + p * 8]);
        d[(size_t)(n0 + ty + p * 8) * K + k0 + tx] = *(unsigned short*)&v;
    }
}

// ---------------- small kernels ----------------
__global__ void zero_counts_kernel() {
    if (threadIdx.x < EE) g_counts[threadIdx.x] = 0;
}

__global__ void rmsnorm_kernel(const float* __restrict__ x,
                               const float* __restrict__ w,
                               float* __restrict__ o,
                               unsigned short* __restrict__ o16) {
    int row = blockIdx.x;
    const float* xr = x + (size_t)row * CC;
    __shared__ float red[8];
    float s = 0.f;
    for (int c = threadIdx.x; c < CC; c += 256) { float v = xr[c]; s += v * v; }
    #pragma unroll
    for (int off = 16; off; off >>= 1) s += __shfl_xor_sync(~0u, s, off);
    if ((threadIdx.x & 31) == 0) red[threadIdx.x >> 5] = s;
    __syncthreads();
    if (threadIdx.x < 8) {
        float t = red[threadIdx.x];
        #pragma unroll
        for (int off = 4; off; off >>= 1) t += __shfl_xor_sync(0xff, t, off);
        if (threadIdx.x == 0) red[0] = t;
    }
    __syncthreads();
    float inv = rsqrtf(red[0] * (1.0f / CC) + EPS);
    for (int c = threadIdx.x; c < CC; c += 256) {
        float v = xr[c] * inv * w[c];
        if (o) o[(size_t)row * CC + c] = v;
        if (o16) {
            __nv_bfloat16 h = __float2bfloat16_rn(v);
            o16[(size_t)row * CC + c] = *(unsigned short*)&h;
        }
    }
}

__global__ void rope_kernel(float* __restrict__ t, int nh) {
    int idx = blockIdx.x * blockDim.x + threadIdx.x;
    int total = NTOK * nh * 32;
    if (idx >= total) return;
    int n = idx / (nh * 32);
    int r = idx - n * (nh * 32);
    int h = r >> 5;
    int d = r & 31;
    int pos = n & (TT - 1);
    float* p = t + ((size_t)n * nh + h) * HD;
    float fr  = __powf(10000.0f, -(float)d * (1.0f / 32.0f));
    float ang = (float)pos * fr;
    float cs = cosf(ang), sn = sinf(ang);
    float x1 = p[d], x2 = p[d + 32];
    p[d]      = x1 * cs - x2 * sn;
    p[d + 32] = x2 * cs + x1 * sn;
}

// ---------------- attention: sliding-window causal, GQA ----------------
#define QT 128
#define KT 32

__global__ __launch_bounds__(QT)
void attn_kernel(const float* __restrict__ q, const float* __restrict__ k,
                 const float* __restrict__ v, float* __restrict__ out) {
    int bh = blockIdx.y;
    int b = bh / NH, h = bh - b * NH;
    int kh = h / (NH / NKV);
    int q0 = blockIdx.x * QT;
    int tid = threadIdx.x;
    int i = q0 + tid;

    __shared__ float Ks[KT][HD];
    __shared__ float Vs[KT][HD];

    float qr[HD];
    const float* qrow = q + ((size_t)(b * TT + i) * NH + h) * HD;
    #pragma unroll
    for (int d = 0; d < HD; d++) qr[d] = qrow[d] * 0.125f;

    float acc[HD];
    #pragma unroll
    for (int d = 0; d < HD; d++) acc[d] = 0.f;
    float mx = -1e30f, l = 0.f;

    int kmin = q0 - WIN + 1; if (kmin < 0) kmin = 0;
    kmin &= ~(KT - 1);
    int kmax = q0 + QT - 1;

    for (int kt = kmin; kt <= kmax; kt += KT) {
        __syncthreads();
        #pragma unroll
        for (int u = 0; u < 4; u++) {
            int idx = tid + u * QT;
            int r = idx >> 4;
            int c = (idx & 15) * 4;
            const float* kr = k + ((size_t)(b * TT + kt + r) * NKV + kh) * HD;
            const float* vr = v + ((size_t)(b * TT + kt + r) * NKV + kh) * HD;
            *(float4*)&Ks[r][c] = *(const float4*)&kr[c];
            *(float4*)&Vs[r][c] = *(const float4*)&vr[c];
        }
        __syncthreads();

        float s[KT];
        float tm = -1e30f;
        #pragma unroll
        for (int kk = 0; kk < KT; kk++) {
            int j = kt + kk;
            bool ok = (j <= i) && (j > i - WIN);
            float d = 0.f;
            #pragma unroll
            for (int dd = 0; dd < HD; dd++) d += qr[dd] * Ks[kk][dd];
            s[kk] = ok ? d : -1e30f;
            tm = fmaxf(tm, s[kk]);
        }
        if (tm > -9e29f) {
            float nm = fmaxf(mx, tm);
            float corr = __expf(mx - nm);
            l *= corr;
            #pragma unroll
            for (int dd = 0; dd < HD; dd++) acc[dd] *= corr;
            #pragma unroll
            for (int kk = 0; kk < KT; kk++) {
                float p = __expf(s[kk] - nm);
                l += p;
                #pragma unroll
                for (int dd = 0; dd < HD; dd++) acc[dd] += p * Vs[kk][dd];
            }
            mx = nm;
        }
    }
    float inv = 1.f / l;
    float* orow = out + ((size_t)(b * TT + i) * NH + h) * HD;
    #pragma unroll
    for (int d = 0; d < HD; d++) orow[d] = acc[d] * inv;
}

// ---------------- MoE routing ----------------
__global__ void route_kernel(const float* __restrict__ g,
                             const float* __restrict__ gw) {
    int warp = (blockIdx.x * blockDim.x + threadIdx.x) >> 5;
    int lane = threadIdx.x & 31;
    if (warp >= NTOK) return;
    const float* row = g + (size_t)warp * CC;
    float acc[EE] = {};
    for (int kk = lane; kk < CC; kk += 32) {
        float gv = row[kk];
        #pragma unroll
        for (int e = 0; e < EE; e++) acc[e] += gv * gw[kk * EE + e];
    }
    #pragma unroll
    for (int e = 0; e < EE; e++)
        #pragma unroll
        for (int off = 16; off; off >>= 1)
            acc[e] += __shfl_xor_sync(~0u, acc[e], off);
    if (lane == 0) {
        int i0 = 0;
        #pragma unroll
        for (int e = 1; e < EE; e++) if (acc[e] > acc[i0]) i0 = e;
        int i1 = -1;
        #pragma unroll
        for (int e = 0; e < EE; e++)
            if (e != i0 && (i1 < 0 || acc[e] > acc[i1])) i1 = e;
        float m  = acc[i0];
        float p1 = __expf(acc[i1] - m);
        float s  = 1.0f + p1;
        float w0 = 1.0f / s, w1 = p1 / s;
        int pos0 = atomicAdd(&g_counts[i0], 1);
        int pos1 = atomicAdd(&g_counts[i1], 1);
        g_tok[i0 * NTOK + pos0] = warp;
        g_tok[i1 * NTOK + pos1] = warp;
        g_tidx[warp * 2 + 0] = i0; g_tidx[warp * 2 + 1] = i1;
        g_tpos[warp * 2 + 0] = pos0; g_tpos[warp * 2 + 1] = pos1;
        g_twt [warp * 2 + 0] = w0;  g_twt [warp * 2 + 1] = w1;
    }
}

// ---------------- final combine ----------------
__global__ void combine_kernel(float* __restrict__ out) {
    int idx = blockIdx.x * blockDim.x + threadIdx.x;
    int n  = idx >> 8;
    int c4 = idx & 255;
    int e0 = g_tidx[n * 2], e1 = g_tidx[n * 2 + 1];
    int p0 = g_tpos[n * 2], p1 = g_tpos[n * 2 + 1];
    float w0 = g_twt[n * 2], w1 = g_twt[n * 2 + 1];
    float4 h4 = ((const float4*)g_hres)[idx];
    float4 a = ((const float4*)(g_moe + ((size_t)e0 * NTOK + p0) * CC))[c4];
    float4 b = ((const float4*)(g_moe + ((size_t)e1 * NTOK + p1) * CC))[c4];
    float4 o;
    o.x = h4.x + w0 * a.x + w1 * b.x;
    o.y = h4.y + w0 * a.y + w1 * b.y;
    o.z = h4.z + w0 * a.z + w1 * b.z;
    o.w = h4.w + w0 * a.w + w1 * b.w;
    ((float4*)out)[idx] = o;
}

// ---------------- launch ----------------
extern "C" void kernel_launch(void* const* d_in, const int* in_sizes, int n_in,
                              void* d_out, int out_size) {
    const float* x           = (const float*)d_in[0];
    const float* attn_norm_w = (const float*)d_in[1];
    const float* ffn_norm_w  = (const float*)d_in[2];
    const float* wq          = (const float*)d_in[3];
    const float* wk          = (const float*)d_in[4];
    const float* wv          = (const float*)d_in[5];
    const float* wo          = (const float*)d_in[6];
    const float* gate_w      = (const float*)d_in[7];
    const float* w1          = (const float*)d_in[8];
    const float* w2          = (const float*)d_in[9];
    const float* w3          = (const float*)d_in[10];
    float* out = (float*)d_out;

    cudaFuncSetAttribute(qkv_gemm,     cudaFuncAttributeMaxDynamicSharedMemorySize, SMEMG);
    cudaFuncSetAttribute(wo_gemm,      cudaFuncAttributeMaxDynamicSharedMemorySize, SMEMG);
    cudaFuncSetAttribute(bf16_gemm<0>, cudaFuncAttributeMaxDynamicSharedMemorySize, SMEM16);
    cudaFuncSetAttribute(bf16_gemm<1>, cudaFuncAttributeMaxDynamicSharedMemorySize, SMEM16);
    cudaFuncSetAttribute(bf16_gemm<2>, cudaFuncAttributeMaxDynamicSharedMemorySize, SMEM16);

    float *hn, *qb, *kb, *vb, *att, *hres, *gbuf, *moe;
    int *tok;
    unsigned short *gb16, *hid16, *w1t, *w2t, *w3t;
    cudaGetSymbolAddress((void**)&hn,    g_hn);
    cudaGetSymbolAddress((void**)&qb,    g_q);
    cudaGetSymbolAddress((void**)&kb,    g_k);
    cudaGetSymbolAddress((void**)&vb,    g_v);
    cudaGetSymbolAddress((void**)&att,   g_att);
    cudaGetSymbolAddress((void**)&hres,  g_hres);
    cudaGetSymbolAddress((void**)&gbuf,  g_gbuf);
    cudaGetSymbolAddress((void**)&moe,   g_moe);
    cudaGetSymbolAddress((void**)&tok,   g_tok);
    cudaGetSymbolAddress((void**)&gb16,  g_gb16);
    cudaGetSymbolAddress((void**)&hid16, g_hid16);
    cudaGetSymbolAddress((void**)&w1t,   g_w1t);
    cudaGetSymbolAddress((void**)&w2t,   g_w2t);
    cudaGetSymbolAddress((void**)&w3t,   g_w3t);

    zero_counts_kernel<<<1, 32>>>();

    // weight transpose+convert (bf16, [N][K])
    transpose_bf16<<<dim3(FF / 32, CC / 32, EE), 256>>>(w1, w1t, CC, FF);
    transpose_bf16<<<dim3(FF / 32, CC / 32, EE), 256>>>(w3, w3t, CC, FF);
    transpose_bf16<<<dim3(CC / 32, FF / 32, EE), 256>>>(w2, w2t, FF, CC);

    rmsnorm_kernel<<<NTOK, 256>>>(x, attn_norm_w, hn, nullptr);

    qkv_gemm<<<dim3(12, 32), 256, SMEMG>>>(hn, wq, wk, wv);

    rope_kernel<<<(NTOK * NH * 32 + 255) / 256, 256>>>(qb, NH);
    rope_kernel<<<(NTOK * NKV * 32 + 255) / 256, 256>>>(kb, NKV);

    attn_kernel<<<dim3(TT / QT, BB * NH), QT>>>(qb, kb, vb, att);

    wo_gemm<<<dim3(8, 32), 256, SMEMG>>>(att, wo, hres, x);

    rmsnorm_kernel<<<NTOK, 256>>>(hres, ffn_norm_w, gbuf, gb16);

    route_kernel<<<NTOK / 8, 256>>>(gbuf, gate_w);

    // MoE pass 1: hid16 = g16 @ w3t (gathered)
    bf16_gemm<1><<<dim3(FF / 128, NTOK / 128, EE), 256, SMEM16>>>(
        gb16, tok, w3t, hid16, CC, FF,
        0, (size_t)CC * FF, (size_t)NTOK * FF);
    // MoE pass 2: hid16 = silu(g16 @ w1t) * hid16
    bf16_gemm<2><<<dim3(FF / 128, NTOK / 128, EE), 256, SMEM16>>>(
        gb16, tok, w1t, hid16, CC, FF,
        0, (size_t)CC * FF, (size_t)NTOK * FF);
    // MoE pass 3: moe(f32) = hid16 @ w2t
    bf16_gemm<0><<<dim3(CC / 128, NTOK / 128, EE), 256, SMEM16>>>(
        hid16, nullptr, w2t, moe, FF, CC,
        (size_t)NTOK * FF, (size_t)FF * CC, (size_t)NTOK * CC);

    combine_kernel<<<(NTOK * CC / 4) / 256, 256>>>(out);
}

// round 6
// speedup vs baseline: 3.5683x; 1.8158x over previous
#include <cuda_runtime.h>
#include <cuda_bf16.h>
#include <cstdint>

// ---------------- problem constants ----------------
#define BB   4
#define TT   1024
#define CC   1024
#define NH   16
#define NKV  4
#define HD   64
#define EE   8
#define FF   4096
#define WIN  256
#define NTOK (BB*TT)          // 4096
#define EPS  1e-6f

// ---------------- scratch ----------------
__device__ float g_hn  [(size_t)NTOK*CC];
__device__ float g_q   [(size_t)NTOK*NH*HD];
__device__ float g_k   [(size_t)NTOK*NKV*HD];
__device__ float g_v   [(size_t)NTOK*NKV*HD];
__device__ float g_att [(size_t)NTOK*CC];
__device__ float g_hres[(size_t)NTOK*CC];
__device__ float g_gbuf[(size_t)NTOK*CC];
__device__ int   g_counts[EE];
__device__ int   g_tok [(size_t)EE*NTOK];
__device__ int   g_tidx[(size_t)NTOK*2];
__device__ int   g_tpos[(size_t)NTOK*2];
__device__ float g_twt [(size_t)NTOK*2];
__device__ float g_moe [(size_t)EE*NTOK*CC];
__device__ unsigned short g_gb16 [(size_t)NTOK*CC];
__device__ unsigned short g_hid16[(size_t)EE*NTOK*FF];
__device__ unsigned short g_w1t  [(size_t)EE*CC*FF];    // [e][FF][CC] bf16
__device__ unsigned short g_w3t  [(size_t)EE*CC*FF];
__device__ unsigned short g_w2t  [(size_t)EE*FF*CC];    // [e][CC][FF] bf16

// ---------------- helpers ----------------
__device__ __forceinline__ uint32_t smem_u32(const void* p) {
    uint32_t a;
    asm("{ .reg .u64 t; cvta.to.shared.u64 t, %1; cvt.u32.u64 %0, t; }" : "=r"(a) : "l"(p));
    return a;
}
__device__ __forceinline__ void cp16(uint32_t dst, const void* src) {
    asm volatile("cp.async.cg.shared.global [%0], [%1], 16;" :: "r"(dst), "l"(src));
}
__device__ __forceinline__ void cp_commit() { asm volatile("cp.async.commit_group;" ::: "memory"); }
__device__ __forceinline__ void cp_wait1() { asm volatile("cp.async.wait_group 1;" ::: "memory"); }
__device__ __forceinline__ void cp_wait2() { asm volatile("cp.async.wait_group 2;" ::: "memory"); }
__device__ __forceinline__ uint32_t f2tf(float f) {
    uint32_t r; asm("cvt.rna.tf32.f32 %0, %1;" : "=r"(r) : "f"(f)); return r;
}
__device__ __forceinline__ void mma8(float* c, const uint32_t* a, const uint32_t* b) {
    asm volatile("mma.sync.aligned.m16n8k8.row.col.f32.tf32.tf32.f32 "
                 "{%0,%1,%2,%3}, {%4,%5,%6,%7}, {%8,%9}, {%0,%1,%2,%3};"
                 : "+f"(c[0]), "+f"(c[1]), "+f"(c[2]), "+f"(c[3])
                 : "r"(a[0]), "r"(a[1]), "r"(a[2]), "r"(a[3]), "r"(b[0]), "r"(b[1]));
}
__device__ __forceinline__ void mma16(float* c, const uint32_t* a, const uint32_t* b) {
    asm volatile("mma.sync.aligned.m16n8k16.row.col.f32.bf16.bf16.f32 "
                 "{%0,%1,%2,%3}, {%4,%5,%6,%7}, {%8,%9}, {%0,%1,%2,%3};"
                 : "+f"(c[0]), "+f"(c[1]), "+f"(c[2]), "+f"(c[3])
                 : "r"(a[0]), "r"(a[1]), "r"(a[2]), "r"(a[3]), "r"(b[0]), "r"(b[1]));
}
__device__ __forceinline__ void ldsm4(uint32_t* r, uint32_t addr) {
    asm volatile("ldmatrix.sync.aligned.m8n8.x4.shared.b16 {%0,%1,%2,%3}, [%4];"
                 : "=r"(r[0]), "=r"(r[1]), "=r"(r[2]), "=r"(r[3]) : "r"(addr));
}

// ================= tf32 GEMM core (attention path) =================
#define NSTG 3
#define ASTRIDE 36
#define BSTRIDE 136
#define ASZ (128*ASTRIDE)
#define BSZ (32*BSTRIDE)
#define SMEMG (NSTG*(ASZ+BSZ)*4)   // 107520 bytes

__device__ __forceinline__ void gemm_body_tf32(
    const float* __restrict__ A, int m0,
    const float* __restrict__ W, float* __restrict__ C, const float* __restrict__ res,
    int K, int Nw, int nloc, float* smf)
{
    float* Abuf[NSTG];
    float* Bbuf[NSTG];
    #pragma unroll
    for (int s = 0; s < NSTG; s++) {
        Abuf[s] = smf + s * ASZ;
        Bbuf[s] = smf + NSTG * ASZ + s * BSZ;
    }
    int tid = threadIdx.x;
    int lane = tid & 31, warp = tid >> 5;
    int wm = warp & 3, wn = warp >> 2;

    int ar = tid >> 1;
    int af = (tid & 1) * 4;
    const float* arow = A + (size_t)(m0 + ar) * K;
    int bk = tid >> 3;
    int bf = tid & 7;
    const float* brow = W + (size_t)bk * Nw + nloc + bf * 4;

    uint32_t aD[NSTG], bD[NSTG];
    #pragma unroll
    for (int p = 0; p < NSTG; p++) {
        aD[p] = smem_u32(Abuf[p]) + (ar * ASTRIDE + af * 4) * 4;
        bD[p] = smem_u32(Bbuf[p]) + (bk * BSTRIDE + bf * 4) * 4;
    }

    auto load_chunk = [&](int ci, int p) {
        const float* as = arow + ci * 32 + af * 4;
        #pragma unroll
        for (int j = 0; j < 4; j++) cp16(aD[p] + j * 16, as + j * 4);
        const float* bs = brow + (size_t)ci * 32 * Nw;
        #pragma unroll
        for (int j = 0; j < 4; j++) cp16(bD[p] + j * 128, bs + j * 32);
    };

    float acc[2][8][4];
    #pragma unroll
    for (int mi = 0; mi < 2; mi++)
        #pragma unroll
        for (int ni = 0; ni < 8; ni++)
            #pragma unroll
            for (int q = 0; q < 4; q++) acc[mi][ni][q] = 0.f;

    int lr = lane >> 2, lc = lane & 3;

    auto compute = [&](int p) {
        const float* Am = Abuf[p];
        const float* Bm = Bbuf[p];
        #pragma unroll
        for (int kk = 0; kk < 4; kk++) {
            int kb = kk * 8;
            uint32_t a[2][4], b[8][2];
            #pragma unroll
            for (int mi = 0; mi < 2; mi++) {
                const float* ap = Am + (wm * 32 + mi * 16 + lr) * ASTRIDE + kb + lc;
                a[mi][0] = f2tf(ap[0]);
                a[mi][1] = f2tf(ap[8 * ASTRIDE]);
                a[mi][2] = f2tf(ap[4]);
                a[mi][3] = f2tf(ap[8 * ASTRIDE + 4]);
            }
            #pragma unroll
            for (int ni = 0; ni < 8; ni++) {
                const float* bp = Bm + (kb + lc) * BSTRIDE + wn * 64 + ni * 8 + lr;
                b[ni][0] = f2tf(bp[0]);
                b[ni][1] = f2tf(bp[4 * BSTRIDE]);
            }
            #pragma unroll
            for (int mi = 0; mi < 2; mi++)
                #pragma unroll
                for (int ni = 0; ni < 8; ni++)
                    mma8(acc[mi][ni], a[mi], b[ni]);
        }
    };

    int NC = K / 32;
    load_chunk(0, 0); cp_commit();
    load_chunk(1, 1); cp_commit();
    for (int i = 0; i < NC; i++) {
        cp_wait1();
        __syncthreads();
        int nx = i + NSTG - 1;
        if (nx < NC) load_chunk(nx, nx % NSTG);
        cp_commit();
        compute(i % NSTG);
    }

    int tc = (lane & 3) * 2;
    #pragma unroll
    for (int mi = 0; mi < 2; mi++) {
        #pragma unroll
        for (int half = 0; half < 2; half++) {
            int m = m0 + wm * 32 + mi * 16 + half * 8 + lr;
            float* crow = C + (size_t)m * Nw + nloc + wn * 64;
            #pragma unroll
            for (int ni = 0; ni < 8; ni++) {
                float c0 = acc[mi][ni][half * 2 + 0];
                float c1 = acc[mi][ni][half * 2 + 1];
                if (res) {
                    const float2 rr = *(const float2*)(res + (size_t)m * Nw + nloc + wn * 64 + ni * 8 + tc);
                    c0 += rr.x; c1 += rr.y;
                }
                float2 v; v.x = c0; v.y = c1;
                *(float2*)(crow + ni * 8 + tc) = v;
            }
        }
    }
}

__global__ __launch_bounds__(256, 2)
void wo_gemm(const float* __restrict__ A, const float* __restrict__ W,
             float* __restrict__ C, const float* __restrict__ res)
{
    extern __shared__ float smf[];
    gemm_body_tf32(A, blockIdx.y * 128, W, C, res, CC, CC, blockIdx.x * 128, smf);
}

__global__ __launch_bounds__(256, 2)
void qkv_gemm(const float* __restrict__ hn,
              const float* __restrict__ wq, const float* __restrict__ wk,
              const float* __restrict__ wv)
{
    extern __shared__ float smf[];
    int m0 = blockIdx.y * 128;
    int nb = blockIdx.x;
    const float* W; float* O; int Nw, nloc;
    if (nb < 8)       { W = wq; O = g_q; Nw = NH * HD;  nloc = nb * 128; }
    else if (nb < 10) { W = wk; O = g_k; Nw = NKV * HD; nloc = (nb - 8) * 128; }
    else              { W = wv; O = g_v; Nw = NKV * HD; nloc = (nb - 10) * 128; }
    gemm_body_tf32(hn, m0, W, O, (const float*)0, CC, Nw, nloc, smf);
}

// ================= bf16 GEMM core (MoE path, ldmatrix) =================
// block tile 128x(128 B-rows)x32, 8 warps (4m x 2n), warp tile 32x64, 4-stage
#define HROW 80                    // bytes per smem row (64B data + 16B pad)
#define HTILE_B (128*HROW)         // 10240 bytes per tile
#define NS16 4
#define SMEM16 (NS16*2*HTILE_B)    // 81920 bytes

// shared mainloop: A rows gathered via list, B rows provided by callback-ish ptr fn
struct Bf16Loop {
    uint32_t sbase;
    int lane, wm, wn;
    uint32_t aR, aK, bR, bK;       // ldmatrix lane geometry
    __device__ __forceinline__ void init(uint32_t sb, int tid) {
        sbase = sb;
        lane = tid & 31;
        int warp = tid >> 5;
        wm = warp & 3; wn = warp >> 2;
        aR = (lane & 7) + ((lane >> 3) & 1) * 8;
        aK = ((lane >> 4) & 1) * 16;
        bR = (lane & 7) + ((lane >> 4) & 1) * 8;
        bK = ((lane >> 3) & 1) * 16;
    }
    __device__ __forceinline__ void compute(int p, float acc[2][8][4]) {
        uint32_t Am = sbase + p * (2 * HTILE_B);
        uint32_t Bm = Am + HTILE_B;
        #pragma unroll
        for (int kk = 0; kk < 2; kk++) {
            uint32_t a[2][4], b[4][4];
            #pragma unroll
            for (int mi = 0; mi < 2; mi++)
                ldsm4(a[mi], Am + (wm * 32 + mi * 16 + aR) * HROW + kk * 32 + aK);
            #pragma unroll
            for (int p2 = 0; p2 < 4; p2++)
                ldsm4(b[p2], Bm + (wn * 64 + p2 * 16 + bR) * HROW + kk * 32 + bK);
            #pragma unroll
            for (int mi = 0; mi < 2; mi++)
                #pragma unroll
                for (int ni = 0; ni < 8; ni++)
                    mma16(acc[mi][ni], a[mi], &b[ni >> 1][(ni & 1) * 2]);
        }
    }
};

// ---- fused MoE pass 1+2: hid[.,c0:c0+64] = silu(g@w1[:,c]) * (g@w3[:,c]) ----
__global__ __launch_bounds__(256, 2)
void moe13_fused()
{
    int e = blockIdx.z;
    int cnt = g_counts[e];
    int m0 = blockIdx.y * 128;
    if (m0 >= cnt) return;
    int c0 = blockIdx.x * 64;     // output column block (64 wide)

    extern __shared__ char smraw[];
    int tid = threadIdx.x;
    uint32_t sbase = smem_u32(smraw);
    Bf16Loop L; L.init(sbase, tid);

    // load geometry: thread -> row (0..127), 2x16B slots
    int row = tid >> 1, sl = (tid & 1) * 2;
    const unsigned short* arow;
    {
        int grow = m0 + row;
        int g2 = (grow < cnt) ? grow : 0;
        arow = g_gb16 + (size_t)g_tok[e * NTOK + g2] * CC;
    }
    const unsigned short* brow = (row < 64)
        ? g_w1t + (size_t)e * CC * FF + (size_t)(c0 + row) * CC
        : g_w3t + (size_t)e * CC * FF + (size_t)(c0 + row - 64) * CC;

    uint32_t aD[NS16], bD[NS16];
    #pragma unroll
    for (int s = 0; s < NS16; s++) {
        aD[s] = sbase + s * (2 * HTILE_B) + row * HROW + sl * 16;
        bD[s] = aD[s] + HTILE_B;
    }
    auto load_chunk = [&](int ci, int p) {
        const unsigned short* as = arow + ci * 32 + sl * 8;
        cp16(aD[p], as); cp16(aD[p] + 16, as + 8);
        const unsigned short* bs = brow + ci * 32 + sl * 8;
        cp16(bD[p], bs); cp16(bD[p] + 16, bs + 8);
    };

    float acc[2][8][4];
    #pragma unroll
    for (int mi = 0; mi < 2; mi++)
        #pragma unroll
        for (int ni = 0; ni < 8; ni++)
            #pragma unroll
            for (int q = 0; q < 4; q++) acc[mi][ni][q] = 0.f;

    const int NC = CC / 32;   // 32
    load_chunk(0, 0); cp_commit();
    load_chunk(1, 1); cp_commit();
    load_chunk(2, 2); cp_commit();
    for (int i = 0; i < NC; i++) {
        cp_wait2();
        __syncthreads();
        int nx = i + NS16 - 1;
        if (nx < NC) load_chunk(nx, nx % NS16);
        cp_commit();
        L.compute(i % NS16, acc);
    }

    // epilogue: warps wn=1 hold the w3 half -> stage to smem, wn=0 combine
    __syncthreads();
    float* eps = (float*)smraw;       // [128][66]
    int lr = L.lane >> 2, lc = L.lane & 3;
    if (L.wn == 1) {
        #pragma unroll
        for (int mi = 0; mi < 2; mi++)
            #pragma unroll
            for (int half = 0; half < 2; half++) {
                int ml = L.wm * 32 + mi * 16 + half * 8 + lr;
                #pragma unroll
                for (int ni = 0; ni < 8; ni++) {
                    eps[ml * 66 + ni * 8 + lc * 2 + 0] = acc[mi][ni][half * 2 + 0];
                    eps[ml * 66 + ni * 8 + lc * 2 + 1] = acc[mi][ni][half * 2 + 1];
                }
            }
    }
    __syncthreads();
    if (L.wn == 0) {
        unsigned short* hrow = g_hid16 + (size_t)e * NTOK * FF + c0;
        #pragma unroll
        for (int mi = 0; mi < 2; mi++)
            #pragma unroll
            for (int half = 0; half < 2; half++) {
                int ml = L.wm * 32 + mi * 16 + half * 8 + lr;
                int m = m0 + ml;
                if (m < cnt) {
                    #pragma unroll
                    for (int ni = 0; ni < 8; ni++) {
                        float x0 = acc[mi][ni][half * 2 + 0];
                        float x1 = acc[mi][ni][half * 2 + 1];
                        float a3x = eps[ml * 66 + ni * 8 + lc * 2 + 0];
                        float a3y = eps[ml * 66 + ni * 8 + lc * 2 + 1];
                        float v0 = x0 / (1.f + __expf(-x0)) * a3x;
                        float v1 = x1 / (1.f + __expf(-x1)) * a3y;
                        __nv_bfloat162 o(__float2bfloat16_rn(v0), __float2bfloat16_rn(v1));
                        *(__nv_bfloat162*)(hrow + (size_t)m * FF + ni * 8 + lc * 2) = o;
                    }
                }
            }
    }
}

// ---- MoE pass 3: moe(f32) = hid16 @ w2t ----
__global__ __launch_bounds__(256, 2)
void moe2_gemm()
{
    int e = blockIdx.z;
    int cnt = g_counts[e];
    int m0 = blockIdx.y * 128;
    if (m0 >= cnt) return;
    int n0 = blockIdx.x * 128;

    extern __shared__ char smraw[];
    int tid = threadIdx.x;
    uint32_t sbase = smem_u32(smraw);
    Bf16Loop L; L.init(sbase, tid);

    int row = tid >> 1, sl = (tid & 1) * 2;
    const unsigned short* arow = g_hid16 + (size_t)e * NTOK * FF + (size_t)(m0 + row) * FF;
    const unsigned short* brow = g_w2t + (size_t)e * FF * CC + (size_t)(n0 + row) * FF;

    uint32_t aD[NS16], bD[NS16];
    #pragma unroll
    for (int s = 0; s < NS16; s++) {
        aD[s] = sbase + s * (2 * HTILE_B) + row * HROW + sl * 16;
        bD[s] = aD[s] + HTILE_B;
    }
    auto load_chunk = [&](int ci, int p) {
        const unsigned short* as = arow + ci * 32 + sl * 8;
        cp16(aD[p], as); cp16(aD[p] + 16, as + 8);
        const unsigned short* bs = brow + ci * 32 + sl * 8;
        cp16(bD[p], bs); cp16(bD[p] + 16, bs + 8);
    };

    float acc[2][8][4];
    #pragma unroll
    for (int mi = 0; mi < 2; mi++)
        #pragma unroll
        for (int ni = 0; ni < 8; ni++)
            #pragma unroll
            for (int q = 0; q < 4; q++) acc[mi][ni][q] = 0.f;

    const int NC = FF / 32;   // 128
    load_chunk(0, 0); cp_commit();
    load_chunk(1, 1); cp_commit();
    load_chunk(2, 2); cp_commit();
    for (int i = 0; i < NC; i++) {
        cp_wait2();
        __syncthreads();
        int nx = i + NS16 - 1;
        if (nx < NC) load_chunk(nx, nx % NS16);
        cp_commit();
        L.compute(i % NS16, acc);
    }

    int lr = L.lane >> 2, lc = L.lane & 3;
    float* Co = g_moe + (size_t)e * NTOK * CC;
    #pragma unroll
    for (int mi = 0; mi < 2; mi++)
        #pragma unroll
        for (int half = 0; half < 2; half++) {
            int m = m0 + L.wm * 32 + mi * 16 + half * 8 + lr;
            if (m < cnt) {
                #pragma unroll
                for (int ni = 0; ni < 8; ni++) {
                    float2 v;
                    v.x = acc[mi][ni][half * 2 + 0];
                    v.y = acc[mi][ni][half * 2 + 1];
                    *(float2*)(Co + (size_t)m * CC + n0 + L.wn * 64 + ni * 8 + lc * 2) = v;
                }
            }
        }
}

// ---------------- weight transpose+convert (all three, one launch) ----------------
__global__ void transpose_all(const float* __restrict__ w1, const float* __restrict__ w3,
                              const float* __restrict__ w2) {
    __shared__ float t[32][33];
    int z = blockIdx.z;               // 0..23
    const float* src; unsigned short* dst; int K, N;
    if (z < 8)       { src = w1 + (size_t)z * CC * FF;        dst = g_w1t + (size_t)z * CC * FF;        K = CC; N = FF; }
    else if (z < 16) { src = w3 + (size_t)(z - 8) * CC * FF;  dst = g_w3t + (size_t)(z - 8) * CC * FF;  K = CC; N = FF; }
    else             { src = w2 + (size_t)(z - 16) * FF * CC; dst = g_w2t + (size_t)(z - 16) * FF * CC; K = FF; N = CC; }
    int nb = N / 32;
    int n0 = (blockIdx.x % nb) * 32;
    int k0 = (blockIdx.x / nb) * 32;
    int tx = threadIdx.x & 31, ty = threadIdx.x >> 5;
    #pragma unroll
    for (int p = 0; p < 4; p++)
        t[ty + p * 8][tx] = src[(size_t)(k0 + ty + p * 8) * N + n0 + tx];
    __syncthreads();
    #pragma unroll
    for (int p = 0; p < 4; p++) {
        __nv_bfloat16 v = __float2bfloat16_rn(t[tx][ty + p * 8]);
        dst[(size_t)(n0 + ty + p * 8) * K + k0 + tx] = *(unsigned short*)&v;
    }
}

// ---------------- small kernels ----------------
__global__ void zero_counts_kernel() {
    if (threadIdx.x < EE) g_counts[threadIdx.x] = 0;
}

__global__ void rmsnorm_kernel(const float* __restrict__ x,
                               const float* __restrict__ w,
                               float* __restrict__ o,
                               unsigned short* __restrict__ o16) {
    int row = blockIdx.x;
    const float* xr = x + (size_t)row * CC;
    __shared__ float red[8];
    float s = 0.f;
    for (int c = threadIdx.x; c < CC; c += 256) { float v = xr[c]; s += v * v; }
    #pragma unroll
    for (int off = 16; off; off >>= 1) s += __shfl_xor_sync(~0u, s, off);
    if ((threadIdx.x & 31) == 0) red[threadIdx.x >> 5] = s;
    __syncthreads();
    if (threadIdx.x < 8) {
        float t = red[threadIdx.x];
        #pragma unroll
        for (int off = 4; off; off >>= 1) t += __shfl_xor_sync(0xff, t, off);
        if (threadIdx.x == 0) red[0] = t;
    }
    __syncthreads();
    float inv = rsqrtf(red[0] * (1.0f / CC) + EPS);
    for (int c = threadIdx.x; c < CC; c += 256) {
        float v = xr[c] * inv * w[c];
        if (o) o[(size_t)row * CC + c] = v;
        if (o16) {
            __nv_bfloat16 h = __float2bfloat16_rn(v);
            o16[(size_t)row * CC + c] = *(unsigned short*)&h;
        }
    }
}

// RoPE over q (NH heads) and k (NKV heads) in one launch
__global__ void rope_all_kernel(float* __restrict__ q, float* __restrict__ k) {
    int idx = blockIdx.x * blockDim.x + threadIdx.x;
    const int qtot = NTOK * NH * 32;
    const int ktot = NTOK * NKV * 32;
    float* t; int nh;
    if (idx < qtot) { t = q; nh = NH; }
    else { idx -= qtot; if (idx >= ktot) return; t = k; nh = NKV; }
    int n = idx / (nh * 32);
    int r = idx - n * (nh * 32);
    int h = r >> 5;
    int d = r & 31;
    int pos = n & (TT - 1);
    float* p = t + ((size_t)n * nh + h) * HD;
    float fr  = __powf(10000.0f, -(float)d * (1.0f / 32.0f));
    float ang = (float)pos * fr;
    float cs = cosf(ang), sn = sinf(ang);
    float x1 = p[d], x2 = p[d + 32];
    p[d]      = x1 * cs - x2 * sn;
    p[d + 32] = x2 * cs + x1 * sn;
}

// ---------------- attention: sliding-window causal, GQA ----------------
#define QT 128
#define KT 32

__global__ __launch_bounds__(QT)
void attn_kernel(const float* __restrict__ q, const float* __restrict__ k,
                 const float* __restrict__ v, float* __restrict__ out) {
    int bh = blockIdx.y;
    int b = bh / NH, h = bh - b * NH;
    int kh = h / (NH / NKV);
    int q0 = blockIdx.x * QT;
    int tid = threadIdx.x;
    int i = q0 + tid;

    __shared__ float Ks[KT][HD];
    __shared__ float Vs[KT][HD];

    float qr[HD];
    const float* qrow = q + ((size_t)(b * TT + i) * NH + h) * HD;
    #pragma unroll
    for (int d = 0; d < HD; d++) qr[d] = qrow[d] * 0.125f;

    float acc[HD];
    #pragma unroll
    for (int d = 0; d < HD; d++) acc[d] = 0.f;
    float mx = -1e30f, l = 0.f;

    int kmin = q0 - WIN + 1; if (kmin < 0) kmin = 0;
    kmin &= ~(KT - 1);
    int kmax = q0 + QT - 1;

    for (int kt = kmin; kt <= kmax; kt += KT) {
        __syncthreads();
        #pragma unroll
        for (int u = 0; u < 4; u++) {
            int idx = tid + u * QT;
            int r = idx >> 4;
            int c = (idx & 15) * 4;
            const float* kr = k + ((size_t)(b * TT + kt + r) * NKV + kh) * HD;
            const float* vr = v + ((size_t)(b * TT + kt + r) * NKV + kh) * HD;
            *(float4*)&Ks[r][c] = *(const float4*)&kr[c];
            *(float4*)&Vs[r][c] = *(const float4*)&vr[c];
        }
        __syncthreads();

        float s[KT];
        float tm = -1e30f;
        #pragma unroll
        for (int kk = 0; kk < KT; kk++) {
            int j = kt + kk;
            bool ok = (j <= i) && (j > i - WIN);
            float d = 0.f;
            #pragma unroll
            for (int dd = 0; dd < HD; dd++) d += qr[dd] * Ks[kk][dd];
            s[kk] = ok ? d : -1e30f;
            tm = fmaxf(tm, s[kk]);
        }
        if (tm > -9e29f) {
            float nm = fmaxf(mx, tm);
            float corr = __expf(mx - nm);
            l *= corr;
            #pragma unroll
            for (int dd = 0; dd < HD; dd++) acc[dd] *= corr;
            #pragma unroll
            for (int kk = 0; kk < KT; kk++) {
                float p = __expf(s[kk] - nm);
                l += p;
                #pragma unroll
                for (int dd = 0; dd < HD; dd++) acc[dd] += p * Vs[kk][dd];
            }
            mx = nm;
        }
    }
    float inv = 1.f / l;
    float* orow = out + ((size_t)(b * TT + i) * NH + h) * HD;
    #pragma unroll
    for (int d = 0; d < HD; d++) orow[d] = acc[d] * inv;
}

// ---------------- MoE routing ----------------
__global__ void route_kernel(const float* __restrict__ g,
                             const float* __restrict__ gw) {
    int warp = (blockIdx.x * blockDim.x + threadIdx.x) >> 5;
    int lane = threadIdx.x & 31;
    if (warp >= NTOK) return;
    const float* row = g + (size_t)warp * CC;
    float acc[EE] = {};
    for (int kk = lane; kk < CC; kk += 32) {
        float gv = row[kk];
        #pragma unroll
        for (int e = 0; e < EE; e++) acc[e] += gv * gw[kk * EE + e];
    }
    #pragma unroll
    for (int e = 0; e < EE; e++)
        #pragma unroll
        for (int off = 16; off; off >>= 1)
            acc[e] += __shfl_xor_sync(~0u, acc[e], off);
    if (lane == 0) {
        int i0 = 0;
        #pragma unroll
        for (int e = 1; e < EE; e++) if (acc[e] > acc[i0]) i0 = e;
        int i1 = -1;
        #pragma unroll
        for (int e = 0; e < EE; e++)
            if (e != i0 && (i1 < 0 || acc[e] > acc[i1])) i1 = e;
        float m  = acc[i0];
        float p1 = __expf(acc[i1] - m);
        float s  = 1.0f + p1;
        float w0 = 1.0f / s, w1 = p1 / s;
        int pos0 = atomicAdd(&g_counts[i0], 1);
        int pos1 = atomicAdd(&g_counts[i1], 1);
        g_tok[i0 * NTOK + pos0] = warp;
        g_tok[i1 * NTOK + pos1] = warp;
        g_tidx[warp * 2 + 0] = i0; g_tidx[warp * 2 + 1] = i1;
        g_tpos[warp * 2 + 0] = pos0; g_tpos[warp * 2 + 1] = pos1;
        g_twt [warp * 2 + 0] = w0;  g_twt [warp * 2 + 1] = w1;
    }
}

// ---------------- final combine ----------------
__global__ void combine_kernel(float* __restrict__ out) {
    int idx = blockIdx.x * blockDim.x + threadIdx.x;
    int n  = idx >> 8;
    int c4 = idx & 255;
    int e0 = g_tidx[n * 2], e1 = g_tidx[n * 2 + 1];
    int p0 = g_tpos[n * 2], p1 = g_tpos[n * 2 + 1];
    float w0 = g_twt[n * 2], w1 = g_twt[n * 2 + 1];
    float4 h4 = ((const float4*)g_hres)[idx];
    float4 a = ((const float4*)(g_moe + ((size_t)e0 * NTOK + p0) * CC))[c4];
    float4 b = ((const float4*)(g_moe + ((size_t)e1 * NTOK + p1) * CC))[c4];
    float4 o;
    o.x = h4.x + w0 * a.x + w1 * b.x;
    o.y = h4.y + w0 * a.y + w1 * b.y;
    o.z = h4.z + w0 * a.z + w1 * b.z;
    o.w = h4.w + w0 * a.w + w1 * b.w;
    ((float4*)out)[idx] = o;
}

// ---------------- launch ----------------
extern "C" void kernel_launch(void* const* d_in, const int* in_sizes, int n_in,
                              void* d_out, int out_size) {
    const float* x           = (const float*)d_in[0];
    const float* attn_norm_w = (const float*)d_in[1];
    const float* ffn_norm_w  = (const float*)d_in[2];
    const float* wq          = (const float*)d_in[3];
    const float* wk          = (const float*)d_in[4];
    const float* wv          = (const float*)d_in[5];
    const float* wo          = (const float*)d_in[6];
    const float* gate_w      = (const float*)d_in[7];
    const float* w1          = (const float*)d_in[8];
    const float* w2          = (const float*)d_in[9];
    const float* w3          = (const float*)d_in[10];
    float* out = (float*)d_out;

    cudaFuncSetAttribute(qkv_gemm,    cudaFuncAttributeMaxDynamicSharedMemorySize, SMEMG);
    cudaFuncSetAttribute(wo_gemm,     cudaFuncAttributeMaxDynamicSharedMemorySize, SMEMG);
    cudaFuncSetAttribute(moe13_fused, cudaFuncAttributeMaxDynamicSharedMemorySize, SMEM16);
    cudaFuncSetAttribute(moe2_gemm,   cudaFuncAttributeMaxDynamicSharedMemorySize, SMEM16);

    float *hn, *qb, *kb, *vb, *att, *hres, *gbuf;
    unsigned short *gb16;
    cudaGetSymbolAddress((void**)&hn,    g_hn);
    cudaGetSymbolAddress((void**)&qb,    g_q);
    cudaGetSymbolAddress((void**)&kb,    g_k);
    cudaGetSymbolAddress((void**)&vb,    g_v);
    cudaGetSymbolAddress((void**)&att,   g_att);
    cudaGetSymbolAddress((void**)&hres,  g_hres);
    cudaGetSymbolAddress((void**)&gbuf,  g_gbuf);
    cudaGetSymbolAddress((void**)&gb16,  g_gb16);

    // 1: weight transpose+convert (all three, bf16 [N][K])
    transpose_all<<<dim3(4096, 1, 24), 256>>>(w1, w3, w2);
    // 2: attn rmsnorm
    rmsnorm_kernel<<<NTOK, 256>>>(x, attn_norm_w, hn, nullptr);
    // 3: fused QKV projections
    qkv_gemm<<<dim3(12, 32), 256, SMEMG>>>(hn, wq, wk, wv);
    // 4: RoPE (q + k, one launch)
    {
        int tot = NTOK * (NH + NKV) * 32;
        rope_all_kernel<<<(tot + 255) / 256, 256>>>(qb, kb);
    }
    // 5: sliding-window attention
    attn_kernel<<<dim3(TT / QT, BB * NH), QT>>>(qb, kb, vb, att);
    // 6: output projection + residual  (ncu -s 5 -c 1 captures this launch)
    wo_gemm<<<dim3(8, 32), 256, SMEMG>>>(att, wo, hres, x);
    // 7: ffn rmsnorm (fp32 + bf16)
    rmsnorm_kernel<<<NTOK, 256>>>(hres, ffn_norm_w, gbuf, gb16);
    // 8: zero counts
    zero_counts_kernel<<<1, 32>>>();
    // 9: routing
    route_kernel<<<NTOK / 8, 256>>>(gbuf, gate_w);
    // 10: fused MoE pass 1+2
    moe13_fused<<<dim3(FF / 64, NTOK / 128, EE), 256, SMEM16>>>();
    // 11: MoE pass 3
    moe2_gemm<<<dim3(CC / 128, NTOK / 128, EE), 256, SMEM16>>>();
    // 12: final combine + residual
    combine_kernel<<<(NTOK * CC / 4) / 256, 256>>>(out);
}

// round 9
// speedup vs baseline: 4.0108x; 1.1240x over previous
#include <cuda_runtime.h>
#include <cuda_bf16.h>
#include <cstdint>

// ---------------- problem constants ----------------
#define BB   4
#define TT   1024
#define CC   1024
#define NH   16
#define NKV  4
#define HD   64
#define EE   8
#define FF   4096
#define WIN  256
#define NTOK (BB*TT)          // 4096
#define EPS  1e-6f

// ---------------- scratch ----------------
__device__ float g_hn  [(size_t)NTOK*CC];
__device__ float g_q   [(size_t)NTOK*NH*HD];
__device__ float g_k   [(size_t)NTOK*NKV*HD];
__device__ float g_v   [(size_t)NTOK*NKV*HD];
__device__ float g_att [(size_t)NTOK*CC];
__device__ float g_hres[(size_t)NTOK*CC];
__device__ float g_gbuf[(size_t)NTOK*CC];
__device__ int   g_counts[EE];
__device__ int   g_tok [(size_t)EE*NTOK];
__device__ int   g_tidx[(size_t)NTOK*2];
__device__ int   g_tpos[(size_t)NTOK*2];
__device__ float g_twt [(size_t)NTOK*2];
__device__ float g_moe [(size_t)EE*NTOK*CC];
__device__ unsigned short g_gb16 [(size_t)NTOK*CC];
__device__ unsigned short g_hid16[(size_t)EE*NTOK*FF];
__device__ unsigned short g_w1t  [(size_t)EE*CC*FF];    // [e][FF][CC] bf16
__device__ unsigned short g_w3t  [(size_t)EE*CC*FF];
__device__ unsigned short g_w2t  [(size_t)EE*FF*CC];    // [e][CC][FF] bf16

// ---------------- helpers ----------------
__device__ __forceinline__ uint32_t smem_u32(const void* p) {
    uint32_t a;
    asm("{ .reg .u64 t; cvta.to.shared.u64 t, %1; cvt.u32.u64 %0, t; }" : "=r"(a) : "l"(p));
    return a;
}
__device__ __forceinline__ void cp16(uint32_t dst, const void* src) {
    asm volatile("cp.async.cg.shared.global [%0], [%1], 16;" :: "r"(dst), "l"(src));
}
__device__ __forceinline__ void cp_commit() { asm volatile("cp.async.commit_group;" ::: "memory"); }
__device__ __forceinline__ void cp_wait1() { asm volatile("cp.async.wait_group 1;" ::: "memory"); }
__device__ __forceinline__ void cp_wait2() { asm volatile("cp.async.wait_group 2;" ::: "memory"); }
__device__ __forceinline__ uint32_t f2tf(float f) {
    uint32_t r; asm("cvt.rna.tf32.f32 %0, %1;" : "=r"(r) : "f"(f)); return r;
}
__device__ __forceinline__ void mma8(float* c, const uint32_t* a, const uint32_t* b) {
    asm volatile("mma.sync.aligned.m16n8k8.row.col.f32.tf32.tf32.f32 "
                 "{%0,%1,%2,%3}, {%4,%5,%6,%7}, {%8,%9}, {%0,%1,%2,%3};"
                 : "+f"(c[0]), "+f"(c[1]), "+f"(c[2]), "+f"(c[3])
                 : "r"(a[0]), "r"(a[1]), "r"(a[2]), "r"(a[3]), "r"(b[0]), "r"(b[1]));
}
__device__ __forceinline__ void mma16(float* c, const uint32_t* a, const uint32_t* b) {
    asm volatile("mma.sync.aligned.m16n8k16.row.col.f32.bf16.bf16.f32 "
                 "{%0,%1,%2,%3}, {%4,%5,%6,%7}, {%8,%9}, {%0,%1,%2,%3};"
                 : "+f"(c[0]), "+f"(c[1]), "+f"(c[2]), "+f"(c[3])
                 : "r"(a[0]), "r"(a[1]), "r"(a[2]), "r"(a[3]), "r"(b[0]), "r"(b[1]));
}
__device__ __forceinline__ void ldsm4(uint32_t* r, uint32_t addr) {
    asm volatile("ldmatrix.sync.aligned.m8n8.x4.shared.b16 {%0,%1,%2,%3}, [%4];"
                 : "=r"(r[0]), "=r"(r[1]), "=r"(r[2]), "=r"(r[3]) : "r"(addr));
}

// ================= tf32 GEMM core (attention path) =================
#define NSTG 3
#define ASTRIDE 36
#define BSTRIDE 136
#define ASZ (128*ASTRIDE)
#define BSZ (32*BSTRIDE)
#define SMEMG (NSTG*(ASZ+BSZ)*4)   // 107520 bytes

__device__ __forceinline__ void gemm_body_tf32(
    const float* __restrict__ A, int m0,
    const float* __restrict__ W, float* __restrict__ C, const float* __restrict__ res,
    int K, int Nw, int nloc, float* smf)
{
    float* Abuf[NSTG];
    float* Bbuf[NSTG];
    #pragma unroll
    for (int s = 0; s < NSTG; s++) {
        Abuf[s] = smf + s * ASZ;
        Bbuf[s] = smf + NSTG * ASZ + s * BSZ;
    }
    int tid = threadIdx.x;
    int lane = tid & 31, warp = tid >> 5;
    int wm = warp & 3, wn = warp >> 2;

    int ar = tid >> 1;
    int af = (tid & 1) * 4;
    const float* arow = A + (size_t)(m0 + ar) * K;
    int bk = tid >> 3;
    int bf = tid & 7;
    const float* brow = W + (size_t)bk * Nw + nloc + bf * 4;

    uint32_t aD[NSTG], bD[NSTG];
    #pragma unroll
    for (int p = 0; p < NSTG; p++) {
        aD[p] = smem_u32(Abuf[p]) + (ar * ASTRIDE + af * 4) * 4;
        bD[p] = smem_u32(Bbuf[p]) + (bk * BSTRIDE + bf * 4) * 4;
    }

    auto load_chunk = [&](int ci, int p) {
        const float* as = arow + ci * 32 + af * 4;
        #pragma unroll
        for (int j = 0; j < 4; j++) cp16(aD[p] + j * 16, as + j * 4);
        const float* bs = brow + (size_t)ci * 32 * Nw;
        #pragma unroll
        for (int j = 0; j < 4; j++) cp16(bD[p] + j * 128, bs + j * 32);
    };

    float acc[2][8][4];
    #pragma unroll
    for (int mi = 0; mi < 2; mi++)
        #pragma unroll
        for (int ni = 0; ni < 8; ni++)
            #pragma unroll
            for (int q = 0; q < 4; q++) acc[mi][ni][q] = 0.f;

    int lr = lane >> 2, lc = lane & 3;

    auto compute = [&](int p) {
        const float* Am = Abuf[p];
        const float* Bm = Bbuf[p];
        #pragma unroll
        for (int kk = 0; kk < 4; kk++) {
            int kb = kk * 8;
            uint32_t a[2][4], b[8][2];
            #pragma unroll
            for (int mi = 0; mi < 2; mi++) {
                const float* ap = Am + (wm * 32 + mi * 16 + lr) * ASTRIDE + kb + lc;
                a[mi][0] = f2tf(ap[0]);
                a[mi][1] = f2tf(ap[8 * ASTRIDE]);
                a[mi][2] = f2tf(ap[4]);
                a[mi][3] = f2tf(ap[8 * ASTRIDE + 4]);
            }
            #pragma unroll
            for (int ni = 0; ni < 8; ni++) {
                const float* bp = Bm + (kb + lc) * BSTRIDE + wn * 64 + ni * 8 + lr;
                b[ni][0] = f2tf(bp[0]);
                b[ni][1] = f2tf(bp[4 * BSTRIDE]);
            }
            #pragma unroll
            for (int mi = 0; mi < 2; mi++)
                #pragma unroll
                for (int ni = 0; ni < 8; ni++)
                    mma8(acc[mi][ni], a[mi], b[ni]);
        }
    };

    int NC = K / 32;
    load_chunk(0, 0); cp_commit();
    load_chunk(1, 1); cp_commit();
    for (int i = 0; i < NC; i++) {
        cp_wait1();
        __syncthreads();
        int nx = i + NSTG - 1;
        if (nx < NC) load_chunk(nx, nx % NSTG);
        cp_commit();
        compute(i % NSTG);
    }

    int tc = (lane & 3) * 2;
    #pragma unroll
    for (int mi = 0; mi < 2; mi++) {
        #pragma unroll
        for (int half = 0; half < 2; half++) {
            int m = m0 + wm * 32 + mi * 16 + half * 8 + lr;
            float* crow = C + (size_t)m * Nw + nloc + wn * 64;
            #pragma unroll
            for (int ni = 0; ni < 8; ni++) {
                float c0 = acc[mi][ni][half * 2 + 0];
                float c1 = acc[mi][ni][half * 2 + 1];
                if (res) {
                    const float2 rr = *(const float2*)(res + (size_t)m * Nw + nloc + wn * 64 + ni * 8 + tc);
                    c0 += rr.x; c1 += rr.y;
                }
                float2 v; v.x = c0; v.y = c1;
                *(float2*)(crow + ni * 8 + tc) = v;
            }
        }
    }
}

__global__ __launch_bounds__(256, 2)
void wo_gemm(const float* __restrict__ A, const float* __restrict__ W,
             float* __restrict__ C, const float* __restrict__ res)
{
    extern __shared__ float smf[];
    gemm_body_tf32(A, blockIdx.y * 128, W, C, res, CC, CC, blockIdx.x * 128, smf);
}

__global__ __launch_bounds__(256, 2)
void qkv_gemm(const float* __restrict__ hn,
              const float* __restrict__ wq, const float* __restrict__ wk,
              const float* __restrict__ wv)
{
    extern __shared__ float smf[];
    int m0 = blockIdx.y * 128;
    int nb = blockIdx.x;
    const float* W; float* O; int Nw, nloc;
    if (nb < 8)       { W = wq; O = g_q; Nw = NH * HD;  nloc = nb * 128; }
    else if (nb < 10) { W = wk; O = g_k; Nw = NKV * HD; nloc = (nb - 8) * 128; }
    else              { W = wv; O = g_v; Nw = NKV * HD; nloc = (nb - 10) * 128; }
    gemm_body_tf32(hn, m0, W, O, (const float*)0, CC, Nw, nloc, smf);
}

// ================= bf16 GEMM core (MoE path, ldmatrix) =================
#define HROW 80
#define HTILE_B (128*HROW)
#define NS16 4
#define SMEM16 (NS16*2*HTILE_B)    // 81920 bytes

struct Bf16Loop {
    uint32_t sbase;
    int lane, wm, wn;
    uint32_t aR, aK, bR, bK;
    __device__ __forceinline__ void init(uint32_t sb, int tid) {
        sbase = sb;
        lane = tid & 31;
        int warp = tid >> 5;
        wm = warp & 3; wn = warp >> 2;
        aR = (lane & 7) + ((lane >> 3) & 1) * 8;
        aK = ((lane >> 4) & 1) * 16;
        bR = (lane & 7) + ((lane >> 4) & 1) * 8;
        bK = ((lane >> 3) & 1) * 16;
    }
    __device__ __forceinline__ void compute(int p, float acc[2][8][4]) {
        uint32_t Am = sbase + p * (2 * HTILE_B);
        uint32_t Bm = Am + HTILE_B;
        #pragma unroll
        for (int kk = 0; kk < 2; kk++) {
            uint32_t a[2][4], b[4][4];
            #pragma unroll
            for (int mi = 0; mi < 2; mi++)
                ldsm4(a[mi], Am + (wm * 32 + mi * 16 + aR) * HROW + kk * 32 + aK);
            #pragma unroll
            for (int p2 = 0; p2 < 4; p2++)
                ldsm4(b[p2], Bm + (wn * 64 + p2 * 16 + bR) * HROW + kk * 32 + bK);
            #pragma unroll
            for (int mi = 0; mi < 2; mi++)
                #pragma unroll
                for (int ni = 0; ni < 8; ni++)
                    mma16(acc[mi][ni], a[mi], &b[ni >> 1][(ni & 1) * 2]);
        }
    }
};

// ---- fused MoE pass 1+2 ----
__global__ __launch_bounds__(256, 2)
void moe13_fused()
{
    int e = blockIdx.z;
    int cnt = g_counts[e];
    int m0 = blockIdx.y * 128;
    if (m0 >= cnt) return;
    int c0 = blockIdx.x * 64;

    extern __shared__ char smraw[];
    int tid = threadIdx.x;
    uint32_t sbase = smem_u32(smraw);
    Bf16Loop L; L.init(sbase, tid);

    int row = tid >> 1, sl = (tid & 1) * 2;
    const unsigned short* arow;
    {
        int grow = m0 + row;
        int g2 = (grow < cnt) ? grow : 0;
        arow = g_gb16 + (size_t)g_tok[e * NTOK + g2] * CC;
    }
    const unsigned short* brow = (row < 64)
        ? g_w1t + (size_t)e * CC * FF + (size_t)(c0 + row) * CC
        : g_w3t + (size_t)e * CC * FF + (size_t)(c0 + row - 64) * CC;

    uint32_t aD[NS16], bD[NS16];
    #pragma unroll
    for (int s = 0; s < NS16; s++) {
        aD[s] = sbase + s * (2 * HTILE_B) + row * HROW + sl * 16;
        bD[s] = aD[s] + HTILE_B;
    }
    auto load_chunk = [&](int ci, int p) {
        const unsigned short* as = arow + ci * 32 + sl * 8;
        cp16(aD[p], as); cp16(aD[p] + 16, as + 8);
        const unsigned short* bs = brow + ci * 32 + sl * 8;
        cp16(bD[p], bs); cp16(bD[p] + 16, bs + 8);
    };

    float acc[2][8][4];
    #pragma unroll
    for (int mi = 0; mi < 2; mi++)
        #pragma unroll
        for (int ni = 0; ni < 8; ni++)
            #pragma unroll
            for (int q = 0; q < 4; q++) acc[mi][ni][q] = 0.f;

    const int NC = CC / 32;
    load_chunk(0, 0); cp_commit();
    load_chunk(1, 1); cp_commit();
    load_chunk(2, 2); cp_commit();
    for (int i = 0; i < NC; i++) {
        cp_wait2();
        __syncthreads();
        int nx = i + NS16 - 1;
        if (nx < NC) load_chunk(nx, nx % NS16);
        cp_commit();
        L.compute(i % NS16, acc);
    }

    __syncthreads();
    float* eps = (float*)smraw;
    int lr = L.lane >> 2, lc = L.lane & 3;
    if (L.wn == 1) {
        #pragma unroll
        for (int mi = 0; mi < 2; mi++)
            #pragma unroll
            for (int half = 0; half < 2; half++) {
                int ml = L.wm * 32 + mi * 16 + half * 8 + lr;
                #pragma unroll
                for (int ni = 0; ni < 8; ni++) {
                    eps[ml * 66 + ni * 8 + lc * 2 + 0] = acc[mi][ni][half * 2 + 0];
                    eps[ml * 66 + ni * 8 + lc * 2 + 1] = acc[mi][ni][half * 2 + 1];
                }
            }
    }
    __syncthreads();
    if (L.wn == 0) {
        unsigned short* hrow = g_hid16 + (size_t)e * NTOK * FF + c0;
        #pragma unroll
        for (int mi = 0; mi < 2; mi++)
            #pragma unroll
            for (int half = 0; half < 2; half++) {
                int ml = L.wm * 32 + mi * 16 + half * 8 + lr;
                int m = m0 + ml;
                if (m < cnt) {
                    #pragma unroll
                    for (int ni = 0; ni < 8; ni++) {
                        float x0 = acc[mi][ni][half * 2 + 0];
                        float x1 = acc[mi][ni][half * 2 + 1];
                        float a3x = eps[ml * 66 + ni * 8 + lc * 2 + 0];
                        float a3y = eps[ml * 66 + ni * 8 + lc * 2 + 1];
                        float v0 = x0 / (1.f + __expf(-x0)) * a3x;
                        float v1 = x1 / (1.f + __expf(-x1)) * a3y;
                        __nv_bfloat162 o(__float2bfloat16_rn(v0), __float2bfloat16_rn(v1));
                        *(__nv_bfloat162*)(hrow + (size_t)m * FF + ni * 8 + lc * 2) = o;
                    }
                }
            }
    }
}

// ---- MoE pass 3 ----
__global__ __launch_bounds__(256, 2)
void moe2_gemm()
{
    int e = blockIdx.z;
    int cnt = g_counts[e];
    int m0 = blockIdx.y * 128;
    if (m0 >= cnt) return;
    int n0 = blockIdx.x * 128;

    extern __shared__ char smraw[];
    int tid = threadIdx.x;
    uint32_t sbase = smem_u32(smraw);
    Bf16Loop L; L.init(sbase, tid);

    int row = tid >> 1, sl = (tid & 1) * 2;
    const unsigned short* arow = g_hid16 + (size_t)e * NTOK * FF + (size_t)(m0 + row) * FF;
    const unsigned short* brow = g_w2t + (size_t)e * FF * CC + (size_t)(n0 + row) * FF;

    uint32_t aD[NS16], bD[NS16];
    #pragma unroll
    for (int s = 0; s < NS16; s++) {
        aD[s] = sbase + s * (2 * HTILE_B) + row * HROW + sl * 16;
        bD[s] = aD[s] + HTILE_B;
    }
    auto load_chunk = [&](int ci, int p) {
        const unsigned short* as = arow + ci * 32 + sl * 8;
        cp16(aD[p], as); cp16(aD[p] + 16, as + 8);
        const unsigned short* bs = brow + ci * 32 + sl * 8;
        cp16(bD[p], bs); cp16(bD[p] + 16, bs + 8);
    };

    float acc[2][8][4];
    #pragma unroll
    for (int mi = 0; mi < 2; mi++)
        #pragma unroll
        for (int ni = 0; ni < 8; ni++)
            #pragma unroll
            for (int q = 0; q < 4; q++) acc[mi][ni][q] = 0.f;

    const int NC = FF / 32;
    load_chunk(0, 0); cp_commit();
    load_chunk(1, 1); cp_commit();
    load_chunk(2, 2); cp_commit();
    for (int i = 0; i < NC; i++) {
        cp_wait2();
        __syncthreads();
        int nx = i + NS16 - 1;
        if (nx < NC) load_chunk(nx, nx % NS16);
        cp_commit();
        L.compute(i % NS16, acc);
    }

    int lr = L.lane >> 2, lc = L.lane & 3;
    float* Co = g_moe + (size_t)e * NTOK * CC;
    #pragma unroll
    for (int mi = 0; mi < 2; mi++)
        #pragma unroll
        for (int half = 0; half < 2; half++) {
            int m = m0 + L.wm * 32 + mi * 16 + half * 8 + lr;
            if (m < cnt) {
                #pragma unroll
                for (int ni = 0; ni < 8; ni++) {
                    float2 v;
                    v.x = acc[mi][ni][half * 2 + 0];
                    v.y = acc[mi][ni][half * 2 + 1];
                    *(float2*)(Co + (size_t)m * CC + n0 + L.wn * 64 + ni * 8 + lc * 2) = v;
                }
            }
        }
}

// ---------------- weight transpose+convert ----------------
__global__ void transpose_all(const float* __restrict__ w1, const float* __restrict__ w3,
                              const float* __restrict__ w2) {
    __shared__ float t[32][33];
    int z = blockIdx.z;
    const float* src; unsigned short* dst; int K, N;
    if (z < 8)       { src = w1 + (size_t)z * CC * FF;        dst = g_w1t + (size_t)z * CC * FF;        K = CC; N = FF; }
    else if (z < 16) { src = w3 + (size_t)(z - 8) * CC * FF;  dst = g_w3t + (size_t)(z - 8) * CC * FF;  K = CC; N = FF; }
    else             { src = w2 + (size_t)(z - 16) * FF * CC; dst = g_w2t + (size_t)(z - 16) * FF * CC; K = FF; N = CC; }
    int nb = N / 32;
    int n0 = (blockIdx.x % nb) * 32;
    int k0 = (blockIdx.x / nb) * 32;
    int tx = threadIdx.x & 31, ty = threadIdx.x >> 5;
    #pragma unroll
    for (int p = 0; p < 4; p++)
        t[ty + p * 8][tx] = src[(size_t)(k0 + ty + p * 8) * N + n0 + tx];
    __syncthreads();
    #pragma unroll
    for (int p = 0; p < 4; p++) {
        __nv_bfloat16 v = __float2bfloat16_rn(t[tx][ty + p * 8]);
        dst[(size_t)(n0 + ty + p * 8) * K + k0 + tx] = *(unsigned short*)&v;
    }
}

// ---------------- small kernels ----------------
__global__ void zero_counts_kernel() {
    if (threadIdx.x < EE) g_counts[threadIdx.x] = 0;
}

__global__ void rmsnorm_kernel(const float* __restrict__ x,
                               const float* __restrict__ w,
                               float* __restrict__ o,
                               unsigned short* __restrict__ o16) {
    int row = blockIdx.x;
    const float* xr = x + (size_t)row * CC;
    __shared__ float red[8];
    float s = 0.f;
    for (int c = threadIdx.x; c < CC; c += 256) { float v = xr[c]; s += v * v; }
    #pragma unroll
    for (int off = 16; off; off >>= 1) s += __shfl_xor_sync(~0u, s, off);
    if ((threadIdx.x & 31) == 0) red[threadIdx.x >> 5] = s;
    __syncthreads();
    if (threadIdx.x < 8) {
        float t = red[threadIdx.x];
        #pragma unroll
        for (int off = 4; off; off >>= 1) t += __shfl_xor_sync(0xff, t, off);
        if (threadIdx.x == 0) red[0] = t;
    }
    __syncthreads();
    float inv = rsqrtf(red[0] * (1.0f / CC) + EPS);
    for (int c = threadIdx.x; c < CC; c += 256) {
        float v = xr[c] * inv * w[c];
        if (o) o[(size_t)row * CC + c] = v;
        if (o16) {
            __nv_bfloat16 h = __float2bfloat16_rn(v);
            o16[(size_t)row * CC + c] = *(unsigned short*)&h;
        }
    }
}

__global__ void rope_all_kernel(float* __restrict__ q, float* __restrict__ k) {
    int idx = blockIdx.x * blockDim.x + threadIdx.x;
    const int qtot = NTOK * NH * 32;
    const int ktot = NTOK * NKV * 32;
    float* t; int nh;
    if (idx < qtot) { t = q; nh = NH; }
    else { idx -= qtot; if (idx >= ktot) return; t = k; nh = NKV; }
    int n = idx / (nh * 32);
    int r = idx - n * (nh * 32);
    int h = r >> 5;
    int d = r & 31;
    int pos = n & (TT - 1);
    float* p = t + ((size_t)n * nh + h) * HD;
    float fr  = __powf(10000.0f, -(float)d * (1.0f / 32.0f));
    float ang = (float)pos * fr;
    float cs = cosf(ang), sn = sinf(ang);
    float x1 = p[d], x2 = p[d + 32];
    p[d]      = x1 * cs - x2 * sn;
    p[d + 32] = x2 * cs + x1 * sn;
}

// ---------------- tensor-core flash attention (tf32) ----------------
// block: 128 q rows of one (b,h); 4 warps, each owns 32 q rows.
#define TSTR 40     // smem row stride in elements

__global__ __launch_bounds__(128, 2)
void attn_mma(const float* __restrict__ q, const float* __restrict__ k,
              const float* __restrict__ v, float* __restrict__ out)
{
    __shared__ float Kt[64 * TSTR];          // [d][j]
    __shared__ float Vt[64 * TSTR];          // [d][j]
    __shared__ uint32_t Psm[4][32 * TSTR];   // per-warp P (tf32 bits) [q][j]

    int bh = blockIdx.y;
    int b = bh >> 4, h = bh & 15;
    int kh = h >> 2;
    int q0 = blockIdx.x * 128;
    int tid = threadIdx.x;
    int warp = tid >> 5, lane = tid & 31;
    int lr = lane >> 2, lc = lane & 3;
    int qw = q0 + warp * 32;

    // ---- Q fragments in registers (scaled, tf32) ----
    uint32_t Qf[2][8][4];
    #pragma unroll
    for (int mi = 0; mi < 2; mi++) {
        const float* qp0 = q + ((size_t)(b * TT + qw + mi * 16 + lr) * NH + h) * HD;
        const float* qp1 = qp0 + (size_t)8 * NH * HD;
        #pragma unroll
        for (int kk = 0; kk < 8; kk++) {
            Qf[mi][kk][0] = f2tf(qp0[kk * 8 + lc] * 0.125f);
            Qf[mi][kk][1] = f2tf(qp1[kk * 8 + lc] * 0.125f);
            Qf[mi][kk][2] = f2tf(qp0[kk * 8 + lc + 4] * 0.125f);
            Qf[mi][kk][3] = f2tf(qp1[kk * 8 + lc + 4] * 0.125f);
        }
    }

    float O[2][8][4];
    #pragma unroll
    for (int mi = 0; mi < 2; mi++)
        #pragma unroll
        for (int ni = 0; ni < 8; ni++)
            #pragma unroll
            for (int c = 0; c < 4; c++) O[mi][ni][c] = 0.f;
    float mrow[2][2] = { {-1e30f, -1e30f}, {-1e30f, -1e30f} };
    float lrow[2][2] = { {0.f, 0.f}, {0.f, 0.f} };

    int kmin = q0 - WIN + 1; if (kmin < 0) kmin = 0;
    kmin &= ~31;
    int kmax = q0 + 127;

    int cj = tid & 31, dg = tid >> 5;
    const float* kr0 = k + ((size_t)(b * TT + cj) * NKV + kh) * HD + dg * 16;
    const float* vr0 = v + ((size_t)(b * TT + cj) * NKV + kh) * HD + dg * 16;

    for (int kt = kmin; kt <= kmax; kt += 32) {
        __syncthreads();
        {
            const float* krp = kr0 + (size_t)kt * NKV * HD;
            const float* vrp = vr0 + (size_t)kt * NKV * HD;
            #pragma unroll
            for (int u = 0; u < 4; u++) {
                float4 kv = *(const float4*)(krp + u * 4);
                float4 vv = *(const float4*)(vrp + u * 4);
                int d0 = dg * 16 + u * 4;
                Kt[(d0 + 0) * TSTR + cj] = kv.x; Kt[(d0 + 1) * TSTR + cj] = kv.y;
                Kt[(d0 + 2) * TSTR + cj] = kv.z; Kt[(d0 + 3) * TSTR + cj] = kv.w;
                Vt[(d0 + 0) * TSTR + cj] = vv.x; Vt[(d0 + 1) * TSTR + cj] = vv.y;
                Vt[(d0 + 2) * TSTR + cj] = vv.z; Vt[(d0 + 3) * TSTR + cj] = vv.w;
            }
        }
        __syncthreads();

        // ---- S = Q K^T ----
        float S[2][4][4];
        #pragma unroll
        for (int mi = 0; mi < 2; mi++)
            #pragma unroll
            for (int nj = 0; nj < 4; nj++)
                #pragma unroll
                for (int c = 0; c < 4; c++) S[mi][nj][c] = 0.f;
        #pragma unroll
        for (int kk = 0; kk < 8; kk++) {
            uint32_t bf[4][2];
            #pragma unroll
            for (int nj = 0; nj < 4; nj++) {
                bf[nj][0] = f2tf(Kt[(kk * 8 + lc) * TSTR + nj * 8 + lr]);
                bf[nj][1] = f2tf(Kt[(kk * 8 + lc + 4) * TSTR + nj * 8 + lr]);
            }
            #pragma unroll
            for (int mi = 0; mi < 2; mi++)
                #pragma unroll
                for (int nj = 0; nj < 4; nj++)
                    mma8(S[mi][nj], Qf[mi][kk], bf[nj]);
        }

        // ---- mask + online softmax + stage P ----
        #pragma unroll
        for (int mi = 0; mi < 2; mi++) {
            #pragma unroll
            for (int h2 = 0; h2 < 2; h2++) {
                int qi = qw + mi * 16 + h2 * 8 + lr;
                float tm = -1e30f;
                #pragma unroll
                for (int nj = 0; nj < 4; nj++) {
                    #pragma unroll
                    for (int c = 0; c < 2; c++) {
                        int j = kt + nj * 8 + lc * 2 + c;
                        bool ok = (j <= qi) && (j > qi - WIN);
                        float sv = ok ? S[mi][nj][h2 * 2 + c] : -1e30f;
                        S[mi][nj][h2 * 2 + c] = sv;
                        tm = fmaxf(tm, sv);
                    }
                }
                tm = fmaxf(tm, __shfl_xor_sync(~0u, tm, 1));
                tm = fmaxf(tm, __shfl_xor_sync(~0u, tm, 2));
                float mn = fmaxf(mrow[mi][h2], tm);
                float corr = __expf(mrow[mi][h2] - mn);
                #pragma unroll
                for (int ni = 0; ni < 8; ni++) {
                    O[mi][ni][h2 * 2 + 0] *= corr;
                    O[mi][ni][h2 * 2 + 1] *= corr;
                }
                float ls = 0.f;
                #pragma unroll
                for (int nj = 0; nj < 4; nj++) {
                    uint2 pp;
                    float sv0 = S[mi][nj][h2 * 2 + 0];
                    float sv1 = S[mi][nj][h2 * 2 + 1];
                    float p0 = (sv0 > -9e29f) ? __expf(sv0 - mn) : 0.f;
                    float p1 = (sv1 > -9e29f) ? __expf(sv1 - mn) : 0.f;
                    ls += p0 + p1;
                    pp.x = f2tf(p0); pp.y = f2tf(p1);
                    *(uint2*)&Psm[warp][(mi * 16 + h2 * 8 + lr) * TSTR + nj * 8 + lc * 2] = pp;
                }
                ls += __shfl_xor_sync(~0u, ls, 1);
                ls += __shfl_xor_sync(~0u, ls, 2);
                lrow[mi][h2] = lrow[mi][h2] * corr + ls;
                mrow[mi][h2] = mn;
            }
        }
        __syncwarp();

        // ---- O += P V ----
        // B[k=j][n=d] = V[j][d] = Vt[d][j]  ->  Vt[(n-index)*TSTR + (k-index)]
        #pragma unroll
        for (int kk = 0; kk < 4; kk++) {
            uint32_t a[2][4], bf[8][2];
            #pragma unroll
            for (int mi = 0; mi < 2; mi++) {
                const uint32_t* ap = &Psm[warp][(mi * 16 + lr) * TSTR + kk * 8 + lc];
                a[mi][0] = ap[0];
                a[mi][1] = ap[8 * TSTR];
                a[mi][2] = ap[4];
                a[mi][3] = ap[8 * TSTR + 4];
            }
            #pragma unroll
            for (int ni = 0; ni < 8; ni++) {
                bf[ni][0] = f2tf(Vt[(ni * 8 + lr) * TSTR + kk * 8 + lc]);
                bf[ni][1] = f2tf(Vt[(ni * 8 + lr) * TSTR + kk * 8 + lc + 4]);
            }
            #pragma unroll
            for (int mi = 0; mi < 2; mi++)
                #pragma unroll
                for (int ni = 0; ni < 8; ni++)
                    mma8(O[mi][ni], a[mi], bf[ni]);
        }
    }

    // ---- epilogue ----
    #pragma unroll
    for (int mi = 0; mi < 2; mi++) {
        #pragma unroll
        for (int h2 = 0; h2 < 2; h2++) {
            int qi = qw + mi * 16 + h2 * 8 + lr;
            float inv = 1.f / lrow[mi][h2];
            float* orow = out + ((size_t)(b * TT + qi) * NH + h) * HD;
            #pragma unroll
            for (int ni = 0; ni < 8; ni++) {
                float2 vv;
                vv.x = O[mi][ni][h2 * 2 + 0] * inv;
                vv.y = O[mi][ni][h2 * 2 + 1] * inv;
                *(float2*)(orow + ni * 8 + lc * 2) = vv;
            }
        }
    }
}

// ---------------- MoE routing ----------------
__global__ void route_kernel(const float* __restrict__ g,
                             const float* __restrict__ gw) {
    int warp = (blockIdx.x * blockDim.x + threadIdx.x) >> 5;
    int lane = threadIdx.x & 31;
    if (warp >= NTOK) return;
    const float* row = g + (size_t)warp * CC;
    float acc[EE] = {};
    for (int kk = lane; kk < CC; kk += 32) {
        float gv = row[kk];
        #pragma unroll
        for (int e = 0; e < EE; e++) acc[e] += gv * gw[kk * EE + e];
    }
    #pragma unroll
    for (int e = 0; e < EE; e++)
        #pragma unroll
        for (int off = 16; off; off >>= 1)
            acc[e] += __shfl_xor_sync(~0u, acc[e], off);
    if (lane == 0) {
        int i0 = 0;
        #pragma unroll
        for (int e = 1; e < EE; e++) if (acc[e] > acc[i0]) i0 = e;
        int i1 = -1;
        #pragma unroll
        for (int e = 0; e < EE; e++)
            if (e != i0 && (i1 < 0 || acc[e] > acc[i1])) i1 = e;
        float m  = acc[i0];
        float p1 = __expf(acc[i1] - m);
        float s  = 1.0f + p1;
        float w0 = 1.0f / s, w1 = p1 / s;
        int pos0 = atomicAdd(&g_counts[i0], 1);
        int pos1 = atomicAdd(&g_counts[i1], 1);
        g_tok[i0 * NTOK + pos0] = warp;
        g_tok[i1 * NTOK + pos1] = warp;
        g_tidx[warp * 2 + 0] = i0; g_tidx[warp * 2 + 1] = i1;
        g_tpos[warp * 2 + 0] = pos0; g_tpos[warp * 2 + 1] = pos1;
        g_twt [warp * 2 + 0] = w0;  g_twt [warp * 2 + 1] = w1;
    }
}

// ---------------- final combine ----------------
__global__ void combine_kernel(float* __restrict__ out) {
    int idx = blockIdx.x * blockDim.x + threadIdx.x;
    int n  = idx >> 8;
    int c4 = idx & 255;
    int e0 = g_tidx[n * 2], e1 = g_tidx[n * 2 + 1];
    int p0 = g_tpos[n * 2], p1 = g_tpos[n * 2 + 1];
    float w0 = g_twt[n * 2], w1 = g_twt[n * 2 + 1];
    float4 h4 = ((const float4*)g_hres)[idx];
    float4 a = ((const float4*)(g_moe + ((size_t)e0 * NTOK + p0) * CC))[c4];
    float4 b = ((const float4*)(g_moe + ((size_t)e1 * NTOK + p1) * CC))[c4];
    float4 o;
    o.x = h4.x + w0 * a.x + w1 * b.x;
    o.y = h4.y + w0 * a.y + w1 * b.y;
    o.z = h4.z + w0 * a.z + w1 * b.z;
    o.w = h4.w + w0 * a.w + w1 * b.w;
    ((float4*)out)[idx] = o;
}

// ---------------- launch ----------------
extern "C" void kernel_launch(void* const* d_in, const int* in_sizes, int n_in,
                              void* d_out, int out_size) {
    const float* x           = (const float*)d_in[0];
    const float* attn_norm_w = (const float*)d_in[1];
    const float* ffn_norm_w  = (const float*)d_in[2];
    const float* wq          = (const float*)d_in[3];
    const float* wk          = (const float*)d_in[4];
    const float* wv          = (const float*)d_in[5];
    const float* wo          = (const float*)d_in[6];
    const float* gate_w      = (const float*)d_in[7];
    const float* w1          = (const float*)d_in[8];
    const float* w2          = (const float*)d_in[9];
    const float* w3          = (const float*)d_in[10];
    float* out = (float*)d_out;

    cudaFuncSetAttribute(qkv_gemm,    cudaFuncAttributeMaxDynamicSharedMemorySize, SMEMG);
    cudaFuncSetAttribute(wo_gemm,     cudaFuncAttributeMaxDynamicSharedMemorySize, SMEMG);
    cudaFuncSetAttribute(moe13_fused, cudaFuncAttributeMaxDynamicSharedMemorySize, SMEM16);
    cudaFuncSetAttribute(moe2_gemm,   cudaFuncAttributeMaxDynamicSharedMemorySize, SMEM16);

    float *hn, *qb, *kb, *vb, *att, *hres, *gbuf;
    unsigned short *gb16;
    cudaGetSymbolAddress((void**)&hn,    g_hn);
    cudaGetSymbolAddress((void**)&qb,    g_q);
    cudaGetSymbolAddress((void**)&kb,    g_k);
    cudaGetSymbolAddress((void**)&vb,    g_v);
    cudaGetSymbolAddress((void**)&att,   g_att);
    cudaGetSymbolAddress((void**)&hres,  g_hres);
    cudaGetSymbolAddress((void**)&gbuf,  g_gbuf);
    cudaGetSymbolAddress((void**)&gb16,  g_gb16);

    // 1: weight transpose+convert
    transpose_all<<<dim3(4096, 1, 24), 256>>>(w1, w3, w2);
    // 2: attn rmsnorm
    rmsnorm_kernel<<<NTOK, 256>>>(x, attn_norm_w, hn, nullptr);
    // 3: fused QKV projections
    qkv_gemm<<<dim3(12, 32), 256, SMEMG>>>(hn, wq, wk, wv);
    // 4: RoPE
    {
        int tot = NTOK * (NH + NKV) * 32;
        rope_all_kernel<<<(tot + 255) / 256, 256>>>(qb, kb);
    }
    // 5: tensor-core sliding-window attention
    attn_mma<<<dim3(TT / 128, BB * NH), 128>>>(qb, kb, vb, att);
    // 6: output projection + residual
    wo_gemm<<<dim3(8, 32), 256, SMEMG>>>(att, wo, hres, x);
    // 7: ffn rmsnorm
    rmsnorm_kernel<<<NTOK, 256>>>(hres, ffn_norm_w, gbuf, gb16);
    // 8: zero counts
    zero_counts_kernel<<<1, 32>>>();
    // 9: routing
    route_kernel<<<NTOK / 8, 256>>>(gbuf, gate_w);
    // 10: fused MoE pass 1+2
    moe13_fused<<<dim3(FF / 64, NTOK / 128, EE), 256, SMEM16>>>();
    // 11: MoE pass 3
    moe2_gemm<<<dim3(CC / 128, NTOK / 128, EE), 256, SMEM16>>>();
    // 12: final combine + residual
    combine_kernel<<<(NTOK * CC / 4) / 256, 256>>>(out);
}